// round 5
// baseline (speedup 1.0000x reference)
#include <cuda_runtime.h>
#include <math.h>
#include <stdint.h>

#define B_    16
#define C_    256
#define N_    1024      // 32*32 tokens
#define NH_   8
#define HD_   32
#define HALF_ 128
#define BH_   (B_*NH_)  // 128
#define TABN_ 3969      // 63*63

typedef unsigned long long u64;

// packed fp32x2 ops (sm_100+; ptxas never auto-generates these)
#define FMA2(d,a,b,c) asm("fma.rn.f32x2 %0, %1, %2, %3;" : "=l"(d) : "l"(a), "l"(b), "l"(c))
#define MUL2(d,a,b)   asm("mul.rn.f32x2 %0, %1, %2;"     : "=l"(d) : "l"(a), "l"(b))
#define PACK2(d,x)    asm("mov.b64 %0, {%1, %1};"        : "=l"(d) : "f"(x))
#define PACKAB(d,lo,hi) asm("mov.b64 %0, {%1, %2};"      : "=l"(d) : "f"(lo), "f"(hi))
#define UNPACK2(lo,hi,p) asm("mov.b64 {%0, %1}, %2;" : "=f"(lo), "=f"(hi) : "l"(p))

// ---- scratch (device globals; no runtime allocation allowed) ----
__device__ float g_q[BH_*N_*HD_];      // 16 MB (stored normalized)
__device__ float g_k[BH_*N_*HD_];      // 16 MB (stored normalized)
__device__ float g_v[BH_*N_*HD_];      // 16 MB
__device__ float g_o[BH_*N_*HD_];      // 16 MB
__device__ float g_tab[TABN_*NH_];     // 127 KB
__device__ float g_biasT[NH_*N_*N_];   // 32 MB, layout [h][m][n]

// ============================================================
// K2: CPB table MLP (launch index 0)
// ============================================================
__global__ void __launch_bounds__(256) tab_kernel(
    const float* __restrict__ w1, const float* __restrict__ b1,
    const float* __restrict__ w2)
{
    __shared__ float w1s[256];
    __shared__ float b1s[128];
    __shared__ float w2s[1024];
    int tid = threadIdx.x;
    if (tid < 256) w1s[tid] = w1[tid];
    if (tid < 128) b1s[tid] = b1[tid];
    for (int i = tid; i < 1024; i += 256) w2s[i] = w2[i];
    __syncthreads();

    int p = blockIdx.x * 256 + tid;
    if (p >= TABN_) return;
    int a = p / 63, b = p % 63;
    float t0 = ((float)(a - 31) / 31.0f) * 3.2f;
    float t1 = ((float)(b - 31) / 31.0f) * 3.2f;
    t0 = copysignf(1.f - __expf(-fabsf(t0)), t0);
    t1 = copysignf(1.f - __expf(-fabsf(t1)), t1);

    float acc[NH_];
    #pragma unroll
    for (int h = 0; h < NH_; h++) acc[h] = 0.f;
    for (int k = 0; k < 128; k++) {
        float hv = fmaxf(w1s[2 * k] * t0 + w1s[2 * k + 1] * t1 + b1s[k], 0.f);
        #pragma unroll
        for (int h = 0; h < NH_; h++) acc[h] += w2s[h * 128 + k] * hv;
    }
    #pragma unroll
    for (int h = 0; h < NH_; h++) g_tab[p * NH_ + h] = acc[h];
}

// ============================================================
// K3: expand bias to [h][m][n] (launch index 1)
// ============================================================
__global__ void __launch_bounds__(256) bias_kernel()
{
    int m = blockIdx.x;
    int n = blockIdx.y * 256 + threadIdx.x;
    int i = n >> 5, j = n & 31;
    int p = m >> 5, q = m & 31;
    int idx = (i - p + 31) * 63 + (j - q + 31);
    const float* t = g_tab + idx * NH_;
    #pragma unroll
    for (int h = 0; h < NH_; h++) {
        float v = 16.f / (1.f + __expf(-t[h]));
        g_biasT[((size_t)h * N_ + m) * N_ + n] = v;
    }
}

// ============================================================
// K0: QKV projection + residual + fused q/k normalization.
// Inner GEMM uses oc-pair-packed weights (u64) + fma.rn.f32x2:
// per inner element: 4 LDS.64(w,broadcast) + 1 LDS(x) + 1 pack + 4 FMA2.
// (launch index 2)
// ============================================================
__global__ void __launch_bounds__(256) qkv_kernel(
    const float* __restrict__ x,
    const float* __restrict__ q1w, const float* __restrict__ q1b,
    const float* __restrict__ q2w, const float* __restrict__ q2b,
    const float* __restrict__ k1w, const float* __restrict__ k1b,
    const float* __restrict__ k2w, const float* __restrict__ k2b,
    const float* __restrict__ v1w, const float* __restrict__ v1b,
    const float* __restrict__ v2w, const float* __restrict__ v2b)
{
    __shared__ float x_s[16][C_];       // 16 KB
    __shared__ u64   w_s2[64][32];      // 16 KB: [oc_pair][ii], packed (w[2p],w[2p+1])
    __shared__ float buf_s[16][264];    // 16.9 KB (padded)

    const int tid  = threadIdx.x;
    const int tok0 = blockIdx.x * 16;
    const int b    = tok0 / N_;
    const int n0   = tok0 % N_;

    // stage x, vectorized over tokens (16 consecutive floats per (b,c) row)
    #pragma unroll
    for (int r = 0; r < 4; r++) {
        int idx = r * 256 + tid;          // 0..1023 float4 slots
        int c = idx >> 2, t4 = (idx & 3) * 4;
        float4 xv = *(const float4*)&x[(b * C_ + c) * N_ + n0 + t4];
        x_s[t4 + 0][c] = xv.x; x_s[t4 + 1][c] = xv.y;
        x_s[t4 + 2][c] = xv.z; x_s[t4 + 3][c] = xv.w;
    }
    __syncthreads();

    const float* Ws[6] = {q1w, q2w, k1w, k2w, v1w, v2w};
    const float* Bs[6] = {q1b, q2b, k1b, k2b, v1b, v2b};

    const int lane  = tid & 31;
    const int warp  = tid >> 5;
    const int t     = lane & 15;
    const int sub   = lane >> 4;
    const int oc0   = warp * 16 + sub * 8;   // 8 consecutive out channels
    const int p0    = oc0 >> 1;              // 4 consecutive oc-pairs

    for (int pair = 0; pair < 3; pair++) {
        for (int half = 0; half < 2; half++) {
            const int m = pair * 2 + half;
            const float* W  = Ws[m];
            const float* bb = Bs[m];

            u64 acc[4];
            #pragma unroll
            for (int u = 0; u < 4; u++) {
                float r0 = x_s[t][half * HALF_ + oc0 + 2*u]     + bb[oc0 + 2*u];
                float r1 = x_s[t][half * HALF_ + oc0 + 2*u + 1] + bb[oc0 + 2*u + 1];
                PACKAB(acc[u], r0, r1);
            }

            for (int ch = 0; ch < 4; ch++) {
                __syncthreads();
                // stage packed weights: 2048 u64 (64 pairs x 32 ii), 8 per thread
                #pragma unroll
                for (int r = 0; r < 8; r++) {
                    int idx = r * 256 + tid;     // 0..2047
                    int p = idx >> 5, ii = idx & 31;
                    float w0 = W[(2*p)     * HALF_ + ch * 32 + ii];
                    float w1 = W[(2*p + 1) * HALF_ + ch * 32 + ii];
                    PACKAB(w_s2[p][ii], w0, w1);
                }
                __syncthreads();
                #pragma unroll 8
                for (int ii = 0; ii < 32; ii++) {
                    u64 xx; PACK2(xx, x_s[t][half * HALF_ + ch * 32 + ii]);
                    #pragma unroll
                    for (int u = 0; u < 4; u++)
                        FMA2(acc[u], w_s2[p0 + u][ii], xx, acc[u]);
                }
            }

            float o[8];
            #pragma unroll
            for (int u = 0; u < 4; u++) UNPACK2(o[2*u], o[2*u+1], acc[u]);

            if (pair < 2) {
                #pragma unroll
                for (int u = 0; u < 8; u++)
                    buf_s[t][half * HALF_ + oc0 + u] = o[u];
            } else {
                const int c    = half * HALF_ + oc0;
                const int head = c >> 5, d = c & 31;
                float* out = g_v + (((b * NH_ + head) * N_) + (n0 + t)) * HD_ + d;
                *(float4*)(out)     = make_float4(o[0], o[1], o[2], o[3]);
                *(float4*)(out + 4) = make_float4(o[4], o[5], o[6], o[7]);
            }
        }

        if (pair < 2) {
            __syncthreads();
            if (tid < 128) {
                const int t2   = tid >> 3;
                const int head = tid & 7;
                float4 r[8];
                float s = 0.f;
                #pragma unroll
                for (int i = 0; i < 8; i++) {
                    r[i] = *(float4*)&buf_s[t2][head * 32 + i * 4];
                    s += r[i].x * r[i].x + r[i].y * r[i].y
                       + r[i].z * r[i].z + r[i].w * r[i].w;
                }
                float inv = 1.f / fmaxf(sqrtf(s), 1e-12f);
                float* dst = (pair == 0 ? g_q : g_k)
                           + (((b * NH_ + head) * N_) + (n0 + t2)) * HD_;
                #pragma unroll
                for (int i = 0; i < 8; i++) {
                    r[i].x *= inv; r[i].y *= inv; r[i].z *= inv; r[i].w *= inv;
                    *(float4*)(dst + i * 4) = r[i];
                }
            }
            __syncthreads();
        }
    }
}

// ============================================================
// K4: attention. 2 queries/thread, f32x2 math, bias via prefetched
// LDG. launch_bounds(128,3): 168-reg cap -> 12 warps/SM.
// (launch index 3 — the ncu slot)
// ============================================================
__global__ void __launch_bounds__(128, 3) attn_kernel(const float* __restrict__ logit_scale)
{
    const int MT = 32;                       // keys per tile
    __shared__ ulonglong2 k_s[MT * 8];       // 4 KB
    __shared__ ulonglong2 v_s[MT * 8];       // 4 KB

    const int tid = threadIdx.x;
    const int bh  = blockIdx.y;
    const int h   = bh & 7;
    const int q0  = blockIdx.x * 256 + tid * 2;

    u64 qa[16], qb[16];
    {
        const ulonglong2* qpa = (const ulonglong2*)(g_q + ((size_t)bh * N_ + q0) * HD_);
        #pragma unroll
        for (int u = 0; u < 8; u++) {
            ulonglong2 t0 = qpa[u];     qa[2*u] = t0.x; qa[2*u+1] = t0.y;
            ulonglong2 t1 = qpa[u + 8]; qb[2*u] = t1.x; qb[2*u+1] = t1.y;
        }
    }

    const float scale = __expf(fminf(logit_scale[h], 4.6051702f)); // log(100)
    const float M = scale + 16.0f;

    u64 oa[16], ob[16];
    #pragma unroll
    for (int u = 0; u < 16; u++) { oa[u] = 0ull; ob[u] = 0ull; }
    float suma = 0.f, sumb = 0.f;

    const ulonglong2* kbase = (const ulonglong2*)(g_k + (size_t)bh * N_ * HD_);
    const ulonglong2* vbase = (const ulonglong2*)(g_v + (size_t)bh * N_ * HD_);
    const float*      bbase = g_biasT + (size_t)h * N_ * N_ + blockIdx.x * 256;

    // bias prefetch ring: 4 keys ahead (covers L2 latency)
    float2 bpre[4];
    #pragma unroll
    for (int i = 0; i < 4; i++)
        bpre[i] = __ldg((const float2*)(bbase + (size_t)i * N_) + tid);

    for (int m0 = 0; m0 < N_; m0 += MT) {
        __syncthreads();
        #pragma unroll
        for (int u = 0; u < 2; u++) {
            k_s[u * 128 + tid] = kbase[m0 * 8 + u * 128 + tid];
            v_s[u * 128 + tid] = vbase[m0 * 8 + u * 128 + tid];
        }
        __syncthreads();

        #pragma unroll 4
        for (int j = 0; j < MT; j++) {
            float2 bij = bpre[j & 3];
            int nr = m0 + j + 4;
            if (nr < N_)
                bpre[j & 3] = __ldg((const float2*)(bbase + (size_t)nr * N_) + tid);

            u64 sa0 = 0ull, sa1 = 0ull, sb0 = 0ull, sb1 = 0ull;
            const ulonglong2* kk = &k_s[j * 8];
            #pragma unroll
            for (int u = 0; u < 4; u++) {
                ulonglong2 k0 = kk[2*u];
                ulonglong2 k1 = kk[2*u+1];
                FMA2(sa0, qa[4*u+0], k0.x, sa0);
                FMA2(sa1, qa[4*u+1], k0.y, sa1);
                FMA2(sb0, qb[4*u+0], k0.x, sb0);
                FMA2(sb1, qb[4*u+1], k0.y, sb1);
                FMA2(sa0, qa[4*u+2], k1.x, sa0);
                FMA2(sa1, qa[4*u+3], k1.y, sa1);
                FMA2(sb0, qb[4*u+2], k1.x, sb0);
                FMA2(sb1, qb[4*u+3], k1.y, sb1);
            }
            float a0l, a0h, a1l, a1h, b0l, b0h, b1l, b1h;
            UNPACK2(a0l, a0h, sa0); UNPACK2(a1l, a1h, sa1);
            UNPACK2(b0l, b0h, sb0); UNPACK2(b1l, b1h, sb1);
            float s_a = (a0l + a0h) + (a1l + a1h);
            float s_b = (b0l + b0h) + (b1l + b1h);

            float pa = __expf(fmaf(s_a, scale, bij.x - M));
            float pb = __expf(fmaf(s_b, scale, bij.y - M));
            suma += pa; sumb += pb;

            u64 pa2, pb2;
            PACK2(pa2, pa); PACK2(pb2, pb);
            const ulonglong2* vv = &v_s[j * 8];
            #pragma unroll
            for (int u = 0; u < 8; u++) {
                ulonglong2 vj = vv[u];
                FMA2(oa[2*u],   pa2, vj.x, oa[2*u]);
                FMA2(oa[2*u+1], pa2, vj.y, oa[2*u+1]);
                FMA2(ob[2*u],   pb2, vj.x, ob[2*u]);
                FMA2(ob[2*u+1], pb2, vj.y, ob[2*u+1]);
            }
        }
    }

    float inva = 1.f / suma, invb = 1.f / sumb;
    u64 ia, ib; PACK2(ia, inva); PACK2(ib, invb);
    ulonglong2* op = (ulonglong2*)(g_o + ((size_t)bh * N_ + q0) * HD_);
    #pragma unroll
    for (int u = 0; u < 8; u++) {
        ulonglong2 ra, rb;
        MUL2(ra.x, oa[2*u], ia); MUL2(ra.y, oa[2*u+1], ia);
        MUL2(rb.x, ob[2*u], ib); MUL2(rb.y, ob[2*u+1], ib);
        op[u]     = ra;
        op[u + 8] = rb;
    }
}

// ============================================================
// K5: output projection (packed-weight f32x2 inner), NCHW output.
// (launch index 4)
// ============================================================
__global__ void __launch_bounds__(256) proj_kernel(
    const float* __restrict__ p1w, const float* __restrict__ p1b,
    const float* __restrict__ p2w, const float* __restrict__ p2b,
    float* __restrict__ out)
{
    __shared__ float o_s[16][C_];       // 16 KB
    __shared__ u64   w_s2[64][16];      // 8 KB: [oc_pair][ii]
    __shared__ float y_s[16][C_];       // 16 KB

    const int tid  = threadIdx.x;
    const int tok0 = blockIdx.x * 16;
    const int b    = tok0 / N_;
    const int n0   = tok0 % N_;

    for (int idx = tid; idx < 16 * C_; idx += 256) {
        int t = idx >> 8, c = idx & 255;
        o_s[t][c] = g_o[(((size_t)b * NH_ + (c >> 5)) * N_ + n0 + t) * HD_ + (c & 31)];
    }
    __syncthreads();

    const float* Ws[2] = {p1w, p2w};
    const float* Bs[2] = {p1b, p2b};

    const int lane = tid & 31;
    const int warp = tid >> 5;
    const int t    = lane & 15;
    const int sub  = lane >> 4;
    const int oc0  = warp * 16 + sub * 8;
    const int p0   = oc0 >> 1;

    for (int m = 0; m < 2; m++) {
        const int half = m;
        const float* W  = Ws[m];
        const float* bb = Bs[m];
        u64 acc[4];
        #pragma unroll
        for (int u = 0; u < 4; u++)
            PACKAB(acc[u], bb[oc0 + 2*u], bb[oc0 + 2*u + 1]);

        for (int ch = 0; ch < 8; ch++) {
            __syncthreads();
            // stage packed weights: 1024 u64 (64 pairs x 16 ii), 4 per thread
            #pragma unroll
            for (int r = 0; r < 4; r++) {
                int idx = r * 256 + tid;      // 0..1023
                int p = idx >> 4, ii = idx & 15;
                float w0 = W[(2*p)     * HALF_ + ch * 16 + ii];
                float w1 = W[(2*p + 1) * HALF_ + ch * 16 + ii];
                PACKAB(w_s2[p][ii], w0, w1);
            }
            __syncthreads();
            #pragma unroll 8
            for (int ii = 0; ii < 16; ii++) {
                u64 xx; PACK2(xx, o_s[t][half * HALF_ + ch * 16 + ii]);
                #pragma unroll
                for (int u = 0; u < 4; u++)
                    FMA2(acc[u], w_s2[p0 + u][ii], xx, acc[u]);
            }
        }
        float o[8];
        #pragma unroll
        for (int u = 0; u < 4; u++) UNPACK2(o[2*u], o[2*u+1], acc[u]);
        #pragma unroll
        for (int u = 0; u < 8; u++) y_s[t][half * HALF_ + oc0 + u] = o[u];
    }
    __syncthreads();

    for (int idx = tid; idx < 16 * C_; idx += 256) {
        int c = idx >> 4, t2 = idx & 15;
        out[((size_t)b * C_ + c) * N_ + n0 + t2] = y_s[t2][c];
    }
}

// ============================================================
extern "C" void kernel_launch(void* const* d_in, const int* in_sizes, int n_in,
                              void* d_out, int out_size)
{
    const float* x    = (const float*)d_in[0];
    const float* q1w  = (const float*)d_in[1];
    const float* q1b  = (const float*)d_in[2];
    const float* q2w  = (const float*)d_in[3];
    const float* q2b  = (const float*)d_in[4];
    const float* k1w  = (const float*)d_in[5];
    const float* k1b  = (const float*)d_in[6];
    const float* k2w  = (const float*)d_in[7];
    const float* k2b  = (const float*)d_in[8];
    const float* v1w  = (const float*)d_in[9];
    const float* v1b  = (const float*)d_in[10];
    const float* v2w  = (const float*)d_in[11];
    const float* v2b  = (const float*)d_in[12];
    const float* p1w  = (const float*)d_in[13];
    const float* p1b  = (const float*)d_in[14];
    const float* p2w  = (const float*)d_in[15];
    const float* p2b  = (const float*)d_in[16];
    const float* ls   = (const float*)d_in[17];
    const float* m1w  = (const float*)d_in[18];
    const float* m1b  = (const float*)d_in[19];
    const float* m2w  = (const float*)d_in[20];
    float* out = (float*)d_out;

    // Order keeps attn_kernel at app-launch index 3 (the ncu slot).
    tab_kernel<<<(TABN_ + 255) / 256, 256>>>(m1w, m1b, m2w);
    bias_kernel<<<dim3(N_, N_ / 256), 256>>>();
    qkv_kernel<<<B_ * N_ / 16, 256>>>(x, q1w, q1b, q2w, q2b,
                                      k1w, k1b, k2w, k2b,
                                      v1w, v1b, v2w, v2b);
    attn_kernel<<<dim3(N_ / 256, BH_), 128>>>(ls);
    proj_kernel<<<B_ * N_ / 16, 256>>>(p1w, p1b, p2w, p2b, out);
}

// round 6
// speedup vs baseline: 1.3686x; 1.3686x over previous
#include <cuda_runtime.h>
#include <cuda_bf16.h>
#include <math.h>
#include <stdint.h>

#define B_    16
#define C_    256
#define N_    1024      // 32*32 tokens
#define NH_   8
#define HD_   32
#define HALF_ 128
#define BH_   (B_*NH_)  // 128
#define TABN_ 3969      // 63*63

typedef unsigned long long u64;
typedef unsigned int u32;

// packed fp32x2 ops (used in qkv/proj GEMMs)
#define FMA2(d,a,b,c) asm("fma.rn.f32x2 %0, %1, %2, %3;" : "=l"(d) : "l"(a), "l"(b), "l"(c))
#define PACK2(d,x)    asm("mov.b64 %0, {%1, %1};"        : "=l"(d) : "f"(x))
#define PACKAB(d,lo,hi) asm("mov.b64 %0, {%1, %2};"      : "=l"(d) : "f"(lo), "f"(hi))
#define UNPACK2(lo,hi,p) asm("mov.b64 {%0, %1}, %2;" : "=f"(lo), "=f"(hi) : "l"(p))

// bf16 mma m16n8k16, fp32 accum
#define MMA16816(d0,d1,d2,d3,a0,a1,a2,a3,b0,b1) \
    asm("mma.sync.aligned.m16n8k16.row.col.f32.bf16.bf16.f32 " \
        "{%0,%1,%2,%3}, {%4,%5,%6,%7}, {%8,%9}, {%0,%1,%2,%3};" \
        : "+f"(d0), "+f"(d1), "+f"(d2), "+f"(d3) \
        : "r"(a0), "r"(a1), "r"(a2), "r"(a3), "r"(b0), "r"(b1))

// ---- scratch (device globals; no runtime allocation allowed) ----
__device__ __nv_bfloat16 g_qs[BH_*N_*96];   // [qh|ql|qh]  25 MB
__device__ __nv_bfloat16 g_ks[BH_*N_*96];   // [kh|kh|kl]  25 MB
__device__ __nv_bfloat16 g_vt[BH_*64*N_];   // [bh][vh(32)+vl(32)][key] 16 MB
__device__ float g_o[BH_*N_*HD_];           // 16 MB
__device__ float g_tab[TABN_*NH_];          // 127 KB
__device__ float g_biasB[NH_*N_*N_];        // 32 MB, layout [h][query][key]

__device__ __forceinline__ u32 pkh(__nv_bfloat16 a, __nv_bfloat16 b) {
    __nv_bfloat162 t; t.x = a; t.y = b;
    return *(u32*)&t;
}
__device__ __forceinline__ u32 pkf(float a, float b) {
    __nv_bfloat162 t = __floats2bfloat162_rn(a, b);
    return *(u32*)&t;
}

// ============================================================
// K2: CPB table MLP (launch index 0)
// ============================================================
__global__ void __launch_bounds__(256) tab_kernel(
    const float* __restrict__ w1, const float* __restrict__ b1,
    const float* __restrict__ w2)
{
    __shared__ float w1s[256];
    __shared__ float b1s[128];
    __shared__ float w2s[1024];
    int tid = threadIdx.x;
    if (tid < 256) w1s[tid] = w1[tid];
    if (tid < 128) b1s[tid] = b1[tid];
    for (int i = tid; i < 1024; i += 256) w2s[i] = w2[i];
    __syncthreads();

    int p = blockIdx.x * 256 + tid;
    if (p >= TABN_) return;
    int a = p / 63, b = p % 63;
    float t0 = ((float)(a - 31) / 31.0f) * 3.2f;
    float t1 = ((float)(b - 31) / 31.0f) * 3.2f;
    t0 = copysignf(1.f - __expf(-fabsf(t0)), t0);
    t1 = copysignf(1.f - __expf(-fabsf(t1)), t1);

    float acc[NH_];
    #pragma unroll
    for (int h = 0; h < NH_; h++) acc[h] = 0.f;
    for (int k = 0; k < 128; k++) {
        float hv = fmaxf(w1s[2 * k] * t0 + w1s[2 * k + 1] * t1 + b1s[k], 0.f);
        #pragma unroll
        for (int h = 0; h < NH_; h++) acc[h] += w2s[h * 128 + k] * hv;
    }
    #pragma unroll
    for (int h = 0; h < NH_; h++) g_tab[p * NH_ + h] = acc[h];
}

// ============================================================
// K3: expand bias to [h][query][key] (launch index 1)
// ============================================================
__global__ void __launch_bounds__(256) bias_kernel()
{
    int n = blockIdx.x;                       // query
    int m = blockIdx.y * 256 + threadIdx.x;   // key
    int i = n >> 5, j = n & 31;               // query coords
    int p = m >> 5, q = m & 31;               // key coords
    int idx = (i - p + 31) * 63 + (j - q + 31);
    const float* t = g_tab + idx * NH_;
    #pragma unroll
    for (int h = 0; h < NH_; h++) {
        float v = 16.f / (1.f + __expf(-t[h]));
        g_biasB[((size_t)h * N_ + n) * N_ + m] = v;
    }
}

// ============================================================
// K0: QKV projection + residual + fused q/k normalization +
// split-bf16 emission (qs/ks K-extended, vt transposed split).
// (launch index 2)
// ============================================================
__global__ void __launch_bounds__(256) qkv_kernel(
    const float* __restrict__ x,
    const float* __restrict__ q1w, const float* __restrict__ q1b,
    const float* __restrict__ q2w, const float* __restrict__ q2b,
    const float* __restrict__ k1w, const float* __restrict__ k1b,
    const float* __restrict__ k2w, const float* __restrict__ k2b,
    const float* __restrict__ v1w, const float* __restrict__ v1b,
    const float* __restrict__ v2w, const float* __restrict__ v2b)
{
    __shared__ float x_s[16][C_];       // 16 KB
    __shared__ u64   w_s2[64][32];      // 16 KB: [oc_pair][ii]
    __shared__ float buf_s[16][264];    // 16.9 KB (padded)

    const int tid  = threadIdx.x;
    const int tok0 = blockIdx.x * 16;
    const int b    = tok0 / N_;
    const int n0   = tok0 % N_;

    #pragma unroll
    for (int r = 0; r < 4; r++) {
        int idx = r * 256 + tid;          // 0..1023 float4 slots
        int c = idx >> 2, t4 = (idx & 3) * 4;
        float4 xv = *(const float4*)&x[(b * C_ + c) * N_ + n0 + t4];
        x_s[t4 + 0][c] = xv.x; x_s[t4 + 1][c] = xv.y;
        x_s[t4 + 2][c] = xv.z; x_s[t4 + 3][c] = xv.w;
    }
    __syncthreads();

    const float* Ws[6] = {q1w, q2w, k1w, k2w, v1w, v2w};
    const float* Bs[6] = {q1b, q2b, k1b, k2b, v1b, v2b};

    const int lane  = tid & 31;
    const int warp  = tid >> 5;
    const int t     = lane & 15;
    const int sub   = lane >> 4;
    const int oc0   = warp * 16 + sub * 8;
    const int p0    = oc0 >> 1;

    for (int pair = 0; pair < 3; pair++) {
        for (int half = 0; half < 2; half++) {
            const int m = pair * 2 + half;
            const float* W  = Ws[m];
            const float* bb = Bs[m];

            u64 acc[4];
            #pragma unroll
            for (int u = 0; u < 4; u++) {
                float r0 = x_s[t][half * HALF_ + oc0 + 2*u]     + bb[oc0 + 2*u];
                float r1 = x_s[t][half * HALF_ + oc0 + 2*u + 1] + bb[oc0 + 2*u + 1];
                PACKAB(acc[u], r0, r1);
            }

            for (int ch = 0; ch < 4; ch++) {
                __syncthreads();
                #pragma unroll
                for (int r = 0; r < 8; r++) {
                    int idx = r * 256 + tid;     // 0..2047
                    int p = idx >> 5, ii = idx & 31;
                    float w0 = W[(2*p)     * HALF_ + ch * 32 + ii];
                    float w1 = W[(2*p + 1) * HALF_ + ch * 32 + ii];
                    PACKAB(w_s2[p][ii], w0, w1);
                }
                __syncthreads();
                #pragma unroll 8
                for (int ii = 0; ii < 32; ii++) {
                    u64 xx; PACK2(xx, x_s[t][half * HALF_ + ch * 32 + ii]);
                    #pragma unroll
                    for (int u = 0; u < 4; u++)
                        FMA2(acc[u], w_s2[p0 + u][ii], xx, acc[u]);
                }
            }

            float o[8];
            #pragma unroll
            for (int u = 0; u < 4; u++) UNPACK2(o[2*u], o[2*u+1], acc[u]);
            #pragma unroll
            for (int u = 0; u < 8; u++)
                buf_s[t][half * HALF_ + oc0 + u] = o[u];
        }

        __syncthreads();
        if (tid < 128) {
            const int t2   = tid >> 3;
            const int head = tid & 7;
            const int bh   = b * NH_ + head;
            const int nn   = n0 + t2;
            float vals[32];
            float s = 0.f;
            #pragma unroll
            for (int i = 0; i < 8; i++) {
                float4 r = *(float4*)&buf_s[t2][head * 32 + i * 4];
                vals[4*i+0] = r.x; vals[4*i+1] = r.y;
                vals[4*i+2] = r.z; vals[4*i+3] = r.w;
                s += r.x*r.x + r.y*r.y + r.z*r.z + r.w*r.w;
            }
            if (pair < 2) {
                float inv = 1.f / fmaxf(sqrtf(s), 1e-12f);
                #pragma unroll
                for (int i = 0; i < 32; i++) vals[i] *= inv;
                u32 hseg[16], lseg[16];
                #pragma unroll
                for (int j = 0; j < 16; j++) {
                    __nv_bfloat16 ha = __float2bfloat16(vals[2*j]);
                    __nv_bfloat16 hb = __float2bfloat16(vals[2*j+1]);
                    float la = vals[2*j]   - __bfloat162float(ha);
                    float lb = vals[2*j+1] - __bfloat162float(hb);
                    hseg[j] = pkh(ha, hb);
                    lseg[j] = pkf(la, lb);
                }
                u32* dst = (u32*)((pair == 0 ? g_qs : g_ks)
                                  + ((size_t)bh * N_ + nn) * 96);
                if (pair == 0) {        // [qh | ql | qh]
                    #pragma unroll
                    for (int j = 0; j < 16; j++) {
                        dst[j] = hseg[j]; dst[16+j] = lseg[j]; dst[32+j] = hseg[j];
                    }
                } else {                // [kh | kh | kl]
                    #pragma unroll
                    for (int j = 0; j < 16; j++) {
                        dst[j] = hseg[j]; dst[16+j] = hseg[j]; dst[32+j] = lseg[j];
                    }
                }
            } else {
                #pragma unroll
                for (int f = 0; f < 32; f++) {
                    __nv_bfloat16 hv = __float2bfloat16(vals[f]);
                    g_vt[((size_t)bh * 64 + f) * N_ + nn] = hv;
                    g_vt[((size_t)bh * 64 + 32 + f) * N_ + nn] =
                        __float2bfloat16(vals[f] - __bfloat162float(hv));
                }
            }
        }
        __syncthreads();
    }
}

// ============================================================
// K4: attention via bf16 mma.sync (split-bf16, fp32 accum).
// grid (8 qtiles x 128 bh), 256 threads (8 warps x m16 = 128 q/block).
// Streaming softmax with constant shift M = scale + 16.
// (launch index 3 — the ncu slot)
// ============================================================
__global__ void __launch_bounds__(256) attn_kernel(const float* __restrict__ logit_scale)
{
    __shared__ __align__(16) __nv_bfloat16 ks_s[64][104];  // 64 keys x 96(+8) feats
    __shared__ __align__(16) __nv_bfloat16 vt_s[64][72];   // 64 feats(vh|vl) x 64(+8) keys

    const int tid  = threadIdx.x;
    const int lane = tid & 31;
    const int w    = tid >> 5;
    const int bh   = blockIdx.y;
    const int h    = bh & 7;
    const int q0   = blockIdx.x * 128;
    const int qr   = q0 + w * 16 + (lane >> 2);   // row r0 (r1 = qr+8)
    const int fc2  = 2 * (lane & 3);

    // Q A-fragments: 6 ksteps x 4 regs (K=96 split layout)
    u32 aQ[6][4];
    {
        const __nv_bfloat16* qb = g_qs + ((size_t)bh * N_ + qr) * 96;
        #pragma unroll
        for (int ks = 0; ks < 6; ks++) {
            int f = fc2 + 16 * ks;
            aQ[ks][0] = *(const u32*)(qb + f);
            aQ[ks][1] = *(const u32*)(qb + 8 * 96 + f);
            aQ[ks][2] = *(const u32*)(qb + f + 8);
            aQ[ks][3] = *(const u32*)(qb + 8 * 96 + f + 8);
        }
    }

    const float scale = __expf(fminf(logit_scale[h], 4.6051702f)); // log(100)
    const float M = scale + 16.0f;

    float o[4][4];
    #pragma unroll
    for (int i = 0; i < 4; i++)
        #pragma unroll
        for (int j = 0; j < 4; j++) o[i][j] = 0.f;
    float s0 = 0.f, s1 = 0.f;

    const float* bias0 = g_biasB + ((size_t)h * N_ + qr) * N_;
    const float* bias1 = bias0 + (size_t)8 * N_;

    for (int kt = 0; kt < 16; kt++) {
        __syncthreads();
        // stage K tile: 64 keys x 96 halves = 768 float4
        {
            const float4* src = (const float4*)(g_ks + ((size_t)bh * N_ + kt * 64) * 96);
            #pragma unroll
            for (int i = 0; i < 3; i++) {
                int idx = i * 256 + tid;          // 0..767
                int key = idx / 12, seg = idx % 12;
                *(float4*)&ks_s[key][seg * 8] = src[key * 12 + seg];
            }
            const float4* vsrc = (const float4*)(g_vt + (size_t)bh * 64 * N_ + kt * 64);
            #pragma unroll
            for (int i = 0; i < 2; i++) {
                int idx = i * 256 + tid;          // 0..511
                int f = idx / 8, seg = idx % 8;
                *(float4*)&vt_s[f][seg * 8] = vsrc[(size_t)f * (N_ / 8) + seg];
            }
        }
        __syncthreads();

        // ---- QK^T: S tile (16 q x 64 keys per warp), K=96 ----
        float c[8][4];
        #pragma unroll
        for (int nt = 0; nt < 8; nt++) {
            c[nt][0] = 0.f; c[nt][1] = 0.f; c[nt][2] = 0.f; c[nt][3] = 0.f;
        }
        #pragma unroll
        for (int ks = 0; ks < 6; ks++) {
            #pragma unroll
            for (int nt = 0; nt < 8; nt++) {
                const __nv_bfloat16* kp = &ks_s[nt * 8 + (lane >> 2)][fc2 + 16 * ks];
                u32 b0 = *(const u32*)kp;
                u32 b1 = *(const u32*)(kp + 8);
                MMA16816(c[nt][0], c[nt][1], c[nt][2], c[nt][3],
                         aQ[ks][0], aQ[ks][1], aQ[ks][2], aQ[ks][3], b0, b1);
            }
        }

        // ---- softmax (constant shift) + split-pack P ----
        u32 aPh[16], aPl[16];
        #pragma unroll
        for (int nt = 0; nt < 8; nt++) {
            int kg = kt * 64 + nt * 8 + fc2;
            float2 bb0 = *(const float2*)(bias0 + kg);
            float2 bb1 = *(const float2*)(bias1 + kg);
            float pv0 = __expf(fmaf(c[nt][0], scale, bb0.x - M));
            float pv1 = __expf(fmaf(c[nt][1], scale, bb0.y - M));
            float pv2 = __expf(fmaf(c[nt][2], scale, bb1.x - M));
            float pv3 = __expf(fmaf(c[nt][3], scale, bb1.y - M));
            s0 += pv0 + pv1;
            s1 += pv2 + pv3;
            __nv_bfloat16 h0 = __float2bfloat16(pv0);
            __nv_bfloat16 h1 = __float2bfloat16(pv1);
            __nv_bfloat16 h2 = __float2bfloat16(pv2);
            __nv_bfloat16 h3 = __float2bfloat16(pv3);
            aPh[nt * 2]     = pkh(h0, h1);
            aPh[nt * 2 + 1] = pkh(h2, h3);
            aPl[nt * 2]     = pkf(pv0 - __bfloat162float(h0), pv1 - __bfloat162float(h1));
            aPl[nt * 2 + 1] = pkf(pv2 - __bfloat162float(h2), pv3 - __bfloat162float(h3));
        }

        // ---- P·V: O += ph*vh + pl*vh + ph*vl ----
        #pragma unroll
        for (int ks = 0; ks < 4; ks++) {
            #pragma unroll
            for (int nt = 0; nt < 4; nt++) {
                const __nv_bfloat16* vp = &vt_s[nt * 8 + (lane >> 2)][fc2 + 16 * ks];
                u32 bh0 = *(const u32*)vp;
                u32 bh1 = *(const u32*)(vp + 8);
                const __nv_bfloat16* vq = &vt_s[32 + nt * 8 + (lane >> 2)][fc2 + 16 * ks];
                u32 bl0 = *(const u32*)vq;
                u32 bl1 = *(const u32*)(vq + 8);
                MMA16816(o[nt][0], o[nt][1], o[nt][2], o[nt][3],
                         aPh[4*ks], aPh[4*ks+1], aPh[4*ks+2], aPh[4*ks+3], bh0, bh1);
                MMA16816(o[nt][0], o[nt][1], o[nt][2], o[nt][3],
                         aPl[4*ks], aPl[4*ks+1], aPl[4*ks+2], aPl[4*ks+3], bh0, bh1);
                MMA16816(o[nt][0], o[nt][1], o[nt][2], o[nt][3],
                         aPh[4*ks], aPh[4*ks+1], aPh[4*ks+2], aPh[4*ks+3], bl0, bl1);
            }
        }
    }

    // row sums: reduce across the 4 lanes of each row group
    s0 += __shfl_xor_sync(0xffffffffu, s0, 1);
    s0 += __shfl_xor_sync(0xffffffffu, s0, 2);
    s1 += __shfl_xor_sync(0xffffffffu, s1, 1);
    s1 += __shfl_xor_sync(0xffffffffu, s1, 2);
    float i0 = 1.f / s0, i1 = 1.f / s1;

    #pragma unroll
    for (int nt = 0; nt < 4; nt++) {
        int dd = nt * 8 + fc2;
        float2 w0 = make_float2(o[nt][0] * i0, o[nt][1] * i0);
        float2 w1 = make_float2(o[nt][2] * i1, o[nt][3] * i1);
        *(float2*)&g_o[((size_t)bh * N_ + qr) * HD_ + dd]     = w0;
        *(float2*)&g_o[((size_t)bh * N_ + qr + 8) * HD_ + dd] = w1;
    }
}

// ============================================================
// K5: output projection (packed-weight f32x2 inner), NCHW output.
// (launch index 4)
// ============================================================
__global__ void __launch_bounds__(256) proj_kernel(
    const float* __restrict__ p1w, const float* __restrict__ p1b,
    const float* __restrict__ p2w, const float* __restrict__ p2b,
    float* __restrict__ out)
{
    __shared__ float o_s[16][C_];       // 16 KB
    __shared__ u64   w_s2[64][16];      // 8 KB
    __shared__ float y_s[16][C_];       // 16 KB

    const int tid  = threadIdx.x;
    const int tok0 = blockIdx.x * 16;
    const int b    = tok0 / N_;
    const int n0   = tok0 % N_;

    for (int idx = tid; idx < 16 * C_; idx += 256) {
        int t = idx >> 8, c = idx & 255;
        o_s[t][c] = g_o[(((size_t)b * NH_ + (c >> 5)) * N_ + n0 + t) * HD_ + (c & 31)];
    }
    __syncthreads();

    const float* Ws[2] = {p1w, p2w};
    const float* Bs[2] = {p1b, p2b};

    const int lane = tid & 31;
    const int warp = tid >> 5;
    const int t    = lane & 15;
    const int sub  = lane >> 4;
    const int oc0  = warp * 16 + sub * 8;
    const int p0   = oc0 >> 1;

    for (int m = 0; m < 2; m++) {
        const int half = m;
        const float* W  = Ws[m];
        const float* bb = Bs[m];
        u64 acc[4];
        #pragma unroll
        for (int u = 0; u < 4; u++)
            PACKAB(acc[u], bb[oc0 + 2*u], bb[oc0 + 2*u + 1]);

        for (int ch = 0; ch < 8; ch++) {
            __syncthreads();
            #pragma unroll
            for (int r = 0; r < 4; r++) {
                int idx = r * 256 + tid;      // 0..1023
                int p = idx >> 4, ii = idx & 15;
                float w0 = W[(2*p)     * HALF_ + ch * 16 + ii];
                float w1 = W[(2*p + 1) * HALF_ + ch * 16 + ii];
                PACKAB(w_s2[p][ii], w0, w1);
            }
            __syncthreads();
            #pragma unroll 8
            for (int ii = 0; ii < 16; ii++) {
                u64 xx; PACK2(xx, o_s[t][half * HALF_ + ch * 16 + ii]);
                #pragma unroll
                for (int u = 0; u < 4; u++)
                    FMA2(acc[u], w_s2[p0 + u][ii], xx, acc[u]);
            }
        }
        float o[8];
        #pragma unroll
        for (int u = 0; u < 4; u++) UNPACK2(o[2*u], o[2*u+1], acc[u]);
        #pragma unroll
        for (int u = 0; u < 8; u++) y_s[t][half * HALF_ + oc0 + u] = o[u];
    }
    __syncthreads();

    for (int idx = tid; idx < 16 * C_; idx += 256) {
        int c = idx >> 4, t2 = idx & 15;
        out[((size_t)b * C_ + c) * N_ + n0 + t2] = y_s[t2][c];
    }
}

// ============================================================
extern "C" void kernel_launch(void* const* d_in, const int* in_sizes, int n_in,
                              void* d_out, int out_size)
{
    const float* x    = (const float*)d_in[0];
    const float* q1w  = (const float*)d_in[1];
    const float* q1b  = (const float*)d_in[2];
    const float* q2w  = (const float*)d_in[3];
    const float* q2b  = (const float*)d_in[4];
    const float* k1w  = (const float*)d_in[5];
    const float* k1b  = (const float*)d_in[6];
    const float* k2w  = (const float*)d_in[7];
    const float* k2b  = (const float*)d_in[8];
    const float* v1w  = (const float*)d_in[9];
    const float* v1b  = (const float*)d_in[10];
    const float* v2w  = (const float*)d_in[11];
    const float* v2b  = (const float*)d_in[12];
    const float* p1w  = (const float*)d_in[13];
    const float* p1b  = (const float*)d_in[14];
    const float* p2w  = (const float*)d_in[15];
    const float* p2b  = (const float*)d_in[16];
    const float* ls   = (const float*)d_in[17];
    const float* m1w  = (const float*)d_in[18];
    const float* m1b  = (const float*)d_in[19];
    const float* m2w  = (const float*)d_in[20];
    float* out = (float*)d_out;

    // Order keeps attn_kernel at app-launch index 3 (the ncu slot).
    tab_kernel<<<(TABN_ + 255) / 256, 256>>>(m1w, m1b, m2w);
    bias_kernel<<<dim3(N_, N_ / 256), 256>>>();
    qkv_kernel<<<B_ * N_ / 16, 256>>>(x, q1w, q1b, q2w, q2b,
                                      k1w, k1b, k2w, k2b,
                                      v1w, v1b, v2w, v2b);
    attn_kernel<<<dim3(N_ / 128, BH_), 256>>>(ls);
    proj_kernel<<<B_ * N_ / 16, 256>>>(p1w, p1b, p2w, p2b, out);
}

// round 7
// speedup vs baseline: 1.8440x; 1.3474x over previous
#include <cuda_runtime.h>
#include <cuda_bf16.h>
#include <math.h>
#include <stdint.h>

#define B_    16
#define C_    256
#define N_    1024      // 32*32 tokens
#define NH_   8
#define HD_   32
#define HALF_ 128
#define BH_   (B_*NH_)  // 128
#define TABN_ 3969      // 63*63

typedef unsigned long long u64;
typedef unsigned int u32;

// packed fp32x2 ops (used in qkv/proj GEMMs)
#define FMA2(d,a,b,c) asm("fma.rn.f32x2 %0, %1, %2, %3;" : "=l"(d) : "l"(a), "l"(b), "l"(c))
#define PACK2(d,x)    asm("mov.b64 %0, {%1, %1};"        : "=l"(d) : "f"(x))
#define PACKAB(d,lo,hi) asm("mov.b64 %0, {%1, %2};"      : "=l"(d) : "f"(lo), "f"(hi))
#define UNPACK2(lo,hi,p) asm("mov.b64 {%0, %1}, %2;" : "=f"(lo), "=f"(hi) : "l"(p))

// bf16 mma m16n8k16, fp32 accum
#define MMA16816(d0,d1,d2,d3,a0,a1,a2,a3,b0,b1) \
    asm("mma.sync.aligned.m16n8k16.row.col.f32.bf16.bf16.f32 " \
        "{%0,%1,%2,%3}, {%4,%5,%6,%7}, {%8,%9}, {%0,%1,%2,%3};" \
        : "+f"(d0), "+f"(d1), "+f"(d2), "+f"(d3) \
        : "r"(a0), "r"(a1), "r"(a2), "r"(a3), "r"(b0), "r"(b1))

// ---- scratch (device globals; no runtime allocation allowed) ----
__device__ __nv_bfloat16 g_qs[BH_*N_*96];   // [qh|ql|qh]  25 MB
__device__ __nv_bfloat16 g_ks[BH_*N_*96];   // [kh|kh|kl]  25 MB
__device__ __nv_bfloat16 g_vt[BH_*64*N_];   // [bh][vh(32)+vl(32)][key] 16 MB
__device__ float g_o[BH_*N_*HD_];           // 16 MB
__device__ float g_tab[TABN_*NH_];          // 127 KB
__device__ float g_biasB[NH_*N_*N_];        // 32 MB, layout [h][query][key]

__device__ __forceinline__ u32 pkh(__nv_bfloat16 a, __nv_bfloat16 b) {
    __nv_bfloat162 t; t.x = a; t.y = b;
    return *(u32*)&t;
}
__device__ __forceinline__ u32 pkf(float a, float b) {
    __nv_bfloat162 t = __floats2bfloat162_rn(a, b);
    return *(u32*)&t;
}

// ============================================================
// K2: CPB table MLP (launch index 0)
// ============================================================
__global__ void __launch_bounds__(256) tab_kernel(
    const float* __restrict__ w1, const float* __restrict__ b1,
    const float* __restrict__ w2)
{
    __shared__ float w1s[256];
    __shared__ float b1s[128];
    __shared__ float w2s[1024];
    int tid = threadIdx.x;
    if (tid < 256) w1s[tid] = w1[tid];
    if (tid < 128) b1s[tid] = b1[tid];
    for (int i = tid; i < 1024; i += 256) w2s[i] = w2[i];
    __syncthreads();

    int p = blockIdx.x * 256 + tid;
    if (p >= TABN_) return;
    int a = p / 63, b = p % 63;
    float t0 = ((float)(a - 31) / 31.0f) * 3.2f;
    float t1 = ((float)(b - 31) / 31.0f) * 3.2f;
    t0 = copysignf(1.f - __expf(-fabsf(t0)), t0);
    t1 = copysignf(1.f - __expf(-fabsf(t1)), t1);

    float acc[NH_];
    #pragma unroll
    for (int h = 0; h < NH_; h++) acc[h] = 0.f;
    for (int k = 0; k < 128; k++) {
        float hv = fmaxf(w1s[2 * k] * t0 + w1s[2 * k + 1] * t1 + b1s[k], 0.f);
        #pragma unroll
        for (int h = 0; h < NH_; h++) acc[h] += w2s[h * 128 + k] * hv;
    }
    #pragma unroll
    for (int h = 0; h < NH_; h++) g_tab[p * NH_ + h] = acc[h];
}

// ============================================================
// K3: expand bias to [h][query][key] (launch index 1)
// ============================================================
__global__ void __launch_bounds__(256) bias_kernel()
{
    int n = blockIdx.x;                       // query
    int m = blockIdx.y * 256 + threadIdx.x;   // key
    int i = n >> 5, j = n & 31;               // query coords
    int p = m >> 5, q = m & 31;               // key coords
    int idx = (i - p + 31) * 63 + (j - q + 31);
    const float* t = g_tab + idx * NH_;
    #pragma unroll
    for (int h = 0; h < NH_; h++) {
        float v = 16.f / (1.f + __expf(-t[h]));
        g_biasB[((size_t)h * N_ + n) * N_ + m] = v;
    }
}

// ============================================================
// K0: QKV projection + residual + fused q/k normalization +
// split-bf16 emission. x_s padded to 257 floats/row: the inner
// broadcast read x_s[t][c] (t=lane&15) is now conflict-free
// (was a 16-way bank conflict at stride 256).
// (launch index 2)
// ============================================================
__global__ void __launch_bounds__(256) qkv_kernel(
    const float* __restrict__ x,
    const float* __restrict__ q1w, const float* __restrict__ q1b,
    const float* __restrict__ q2w, const float* __restrict__ q2b,
    const float* __restrict__ k1w, const float* __restrict__ k1b,
    const float* __restrict__ k2w, const float* __restrict__ k2b,
    const float* __restrict__ v1w, const float* __restrict__ v1b,
    const float* __restrict__ v2w, const float* __restrict__ v2b)
{
    __shared__ float x_s[16][C_ + 1];   // padded: conflict-free column reads
    __shared__ u64   w_s2[64][32];      // 16 KB: [oc_pair][ii]
    __shared__ float buf_s[16][264];    // padded

    const int tid  = threadIdx.x;
    const int tok0 = blockIdx.x * 16;
    const int b    = tok0 / N_;
    const int n0   = tok0 % N_;

    #pragma unroll
    for (int r = 0; r < 4; r++) {
        int idx = r * 256 + tid;          // 0..1023 float4 slots
        int c = idx >> 2, t4 = (idx & 3) * 4;
        float4 xv = *(const float4*)&x[(b * C_ + c) * N_ + n0 + t4];
        x_s[t4 + 0][c] = xv.x; x_s[t4 + 1][c] = xv.y;
        x_s[t4 + 2][c] = xv.z; x_s[t4 + 3][c] = xv.w;
    }
    __syncthreads();

    const float* Ws[6] = {q1w, q2w, k1w, k2w, v1w, v2w};
    const float* Bs[6] = {q1b, q2b, k1b, k2b, v1b, v2b};

    const int lane  = tid & 31;
    const int warp  = tid >> 5;
    const int t     = lane & 15;
    const int sub   = lane >> 4;
    const int oc0   = warp * 16 + sub * 8;
    const int p0    = oc0 >> 1;

    for (int pair = 0; pair < 3; pair++) {
        for (int half = 0; half < 2; half++) {
            const int m = pair * 2 + half;
            const float* W  = Ws[m];
            const float* bb = Bs[m];

            u64 acc[4];
            #pragma unroll
            for (int u = 0; u < 4; u++) {
                float r0 = x_s[t][half * HALF_ + oc0 + 2*u]     + bb[oc0 + 2*u];
                float r1 = x_s[t][half * HALF_ + oc0 + 2*u + 1] + bb[oc0 + 2*u + 1];
                PACKAB(acc[u], r0, r1);
            }

            for (int ch = 0; ch < 4; ch++) {
                __syncthreads();
                #pragma unroll
                for (int r = 0; r < 8; r++) {
                    int idx = r * 256 + tid;     // 0..2047
                    int p = idx >> 5, ii = idx & 31;
                    float w0 = W[(2*p)     * HALF_ + ch * 32 + ii];
                    float w1 = W[(2*p + 1) * HALF_ + ch * 32 + ii];
                    PACKAB(w_s2[p][ii], w0, w1);
                }
                __syncthreads();
                #pragma unroll 8
                for (int ii = 0; ii < 32; ii++) {
                    u64 xx; PACK2(xx, x_s[t][half * HALF_ + ch * 32 + ii]);
                    #pragma unroll
                    for (int u = 0; u < 4; u++)
                        FMA2(acc[u], w_s2[p0 + u][ii], xx, acc[u]);
                }
            }

            float o[8];
            #pragma unroll
            for (int u = 0; u < 4; u++) UNPACK2(o[2*u], o[2*u+1], acc[u]);
            #pragma unroll
            for (int u = 0; u < 8; u++)
                buf_s[t][half * HALF_ + oc0 + u] = o[u];
        }

        __syncthreads();
        if (tid < 128) {
            const int t2   = tid >> 3;
            const int head = tid & 7;
            const int bh   = b * NH_ + head;
            const int nn   = n0 + t2;
            float vals[32];
            float s = 0.f;
            #pragma unroll
            for (int i = 0; i < 8; i++) {
                float4 r = *(float4*)&buf_s[t2][head * 32 + i * 4];
                vals[4*i+0] = r.x; vals[4*i+1] = r.y;
                vals[4*i+2] = r.z; vals[4*i+3] = r.w;
                s += r.x*r.x + r.y*r.y + r.z*r.z + r.w*r.w;
            }
            if (pair < 2) {
                float inv = 1.f / fmaxf(sqrtf(s), 1e-12f);
                #pragma unroll
                for (int i = 0; i < 32; i++) vals[i] *= inv;
                u32 hseg[16], lseg[16];
                #pragma unroll
                for (int j = 0; j < 16; j++) {
                    __nv_bfloat16 ha = __float2bfloat16(vals[2*j]);
                    __nv_bfloat16 hb = __float2bfloat16(vals[2*j+1]);
                    float la = vals[2*j]   - __bfloat162float(ha);
                    float lb = vals[2*j+1] - __bfloat162float(hb);
                    hseg[j] = pkh(ha, hb);
                    lseg[j] = pkf(la, lb);
                }
                u32* dst = (u32*)((pair == 0 ? g_qs : g_ks)
                                  + ((size_t)bh * N_ + nn) * 96);
                if (pair == 0) {        // [qh | ql | qh]
                    #pragma unroll
                    for (int j = 0; j < 16; j++) {
                        dst[j] = hseg[j]; dst[16+j] = lseg[j]; dst[32+j] = hseg[j];
                    }
                } else {                // [kh | kh | kl]
                    #pragma unroll
                    for (int j = 0; j < 16; j++) {
                        dst[j] = hseg[j]; dst[16+j] = hseg[j]; dst[32+j] = lseg[j];
                    }
                }
            } else {
                #pragma unroll
                for (int f = 0; f < 32; f++) {
                    __nv_bfloat16 hv = __float2bfloat16(vals[f]);
                    g_vt[((size_t)bh * 64 + f) * N_ + nn] = hv;
                    g_vt[((size_t)bh * 64 + 32 + f) * N_ + nn] =
                        __float2bfloat16(vals[f] - __bfloat162float(hv));
                }
            }
        }
        __syncthreads();
    }
}

// ============================================================
// K4: attention via bf16 mma.sync (split-bf16, fp32 accum).
// grid (8 qtiles x 128 bh), 256 threads (8 warps x m16 = 128 q/block).
// (launch index 3 — the ncu slot)
// ============================================================
__global__ void __launch_bounds__(256) attn_kernel(const float* __restrict__ logit_scale)
{
    __shared__ __align__(16) __nv_bfloat16 ks_s[64][104];  // 64 keys x 96(+8) feats
    __shared__ __align__(16) __nv_bfloat16 vt_s[64][72];   // 64 feats(vh|vl) x 64(+8) keys

    const int tid  = threadIdx.x;
    const int lane = tid & 31;
    const int w    = tid >> 5;
    const int bh   = blockIdx.y;
    const int h    = bh & 7;
    const int q0   = blockIdx.x * 128;
    const int qr   = q0 + w * 16 + (lane >> 2);   // row r0 (r1 = qr+8)
    const int fc2  = 2 * (lane & 3);

    // Q A-fragments: 6 ksteps x 4 regs (K=96 split layout)
    u32 aQ[6][4];
    {
        const __nv_bfloat16* qb = g_qs + ((size_t)bh * N_ + qr) * 96;
        #pragma unroll
        for (int ks = 0; ks < 6; ks++) {
            int f = fc2 + 16 * ks;
            aQ[ks][0] = *(const u32*)(qb + f);
            aQ[ks][1] = *(const u32*)(qb + 8 * 96 + f);
            aQ[ks][2] = *(const u32*)(qb + f + 8);
            aQ[ks][3] = *(const u32*)(qb + 8 * 96 + f + 8);
        }
    }

    const float scale = __expf(fminf(logit_scale[h], 4.6051702f)); // log(100)
    const float M = scale + 16.0f;

    float o[4][4];
    #pragma unroll
    for (int i = 0; i < 4; i++)
        #pragma unroll
        for (int j = 0; j < 4; j++) o[i][j] = 0.f;
    float s0 = 0.f, s1 = 0.f;

    const float* bias0 = g_biasB + ((size_t)h * N_ + qr) * N_;
    const float* bias1 = bias0 + (size_t)8 * N_;

    for (int kt = 0; kt < 16; kt++) {
        __syncthreads();
        {
            const float4* src = (const float4*)(g_ks + ((size_t)bh * N_ + kt * 64) * 96);
            #pragma unroll
            for (int i = 0; i < 3; i++) {
                int idx = i * 256 + tid;          // 0..767
                int key = idx / 12, seg = idx % 12;
                *(float4*)&ks_s[key][seg * 8] = src[key * 12 + seg];
            }
            const float4* vsrc = (const float4*)(g_vt + (size_t)bh * 64 * N_ + kt * 64);
            #pragma unroll
            for (int i = 0; i < 2; i++) {
                int idx = i * 256 + tid;          // 0..511
                int f = idx / 8, seg = idx % 8;
                *(float4*)&vt_s[f][seg * 8] = vsrc[(size_t)f * (N_ / 8) + seg];
            }
        }
        __syncthreads();

        // ---- QK^T: S tile (16 q x 64 keys per warp), K=96 ----
        float c[8][4];
        #pragma unroll
        for (int nt = 0; nt < 8; nt++) {
            c[nt][0] = 0.f; c[nt][1] = 0.f; c[nt][2] = 0.f; c[nt][3] = 0.f;
        }
        #pragma unroll
        for (int ks = 0; ks < 6; ks++) {
            #pragma unroll
            for (int nt = 0; nt < 8; nt++) {
                const __nv_bfloat16* kp = &ks_s[nt * 8 + (lane >> 2)][fc2 + 16 * ks];
                u32 b0 = *(const u32*)kp;
                u32 b1 = *(const u32*)(kp + 8);
                MMA16816(c[nt][0], c[nt][1], c[nt][2], c[nt][3],
                         aQ[ks][0], aQ[ks][1], aQ[ks][2], aQ[ks][3], b0, b1);
            }
        }

        // ---- softmax (constant shift) + split-pack P ----
        u32 aPh[16], aPl[16];
        #pragma unroll
        for (int nt = 0; nt < 8; nt++) {
            int kg = kt * 64 + nt * 8 + fc2;
            float2 bb0 = *(const float2*)(bias0 + kg);
            float2 bb1 = *(const float2*)(bias1 + kg);
            float pv0 = __expf(fmaf(c[nt][0], scale, bb0.x - M));
            float pv1 = __expf(fmaf(c[nt][1], scale, bb0.y - M));
            float pv2 = __expf(fmaf(c[nt][2], scale, bb1.x - M));
            float pv3 = __expf(fmaf(c[nt][3], scale, bb1.y - M));
            s0 += pv0 + pv1;
            s1 += pv2 + pv3;
            __nv_bfloat16 h0 = __float2bfloat16(pv0);
            __nv_bfloat16 h1 = __float2bfloat16(pv1);
            __nv_bfloat16 h2 = __float2bfloat16(pv2);
            __nv_bfloat16 h3 = __float2bfloat16(pv3);
            aPh[nt * 2]     = pkh(h0, h1);
            aPh[nt * 2 + 1] = pkh(h2, h3);
            aPl[nt * 2]     = pkf(pv0 - __bfloat162float(h0), pv1 - __bfloat162float(h1));
            aPl[nt * 2 + 1] = pkf(pv2 - __bfloat162float(h2), pv3 - __bfloat162float(h3));
        }

        // ---- P·V: O += ph*vh + pl*vh + ph*vl ----
        #pragma unroll
        for (int ks = 0; ks < 4; ks++) {
            #pragma unroll
            for (int nt = 0; nt < 4; nt++) {
                const __nv_bfloat16* vp = &vt_s[nt * 8 + (lane >> 2)][fc2 + 16 * ks];
                u32 bh0 = *(const u32*)vp;
                u32 bh1 = *(const u32*)(vp + 8);
                const __nv_bfloat16* vq = &vt_s[32 + nt * 8 + (lane >> 2)][fc2 + 16 * ks];
                u32 bl0 = *(const u32*)vq;
                u32 bl1 = *(const u32*)(vq + 8);
                MMA16816(o[nt][0], o[nt][1], o[nt][2], o[nt][3],
                         aPh[4*ks], aPh[4*ks+1], aPh[4*ks+2], aPh[4*ks+3], bh0, bh1);
                MMA16816(o[nt][0], o[nt][1], o[nt][2], o[nt][3],
                         aPl[4*ks], aPl[4*ks+1], aPl[4*ks+2], aPl[4*ks+3], bh0, bh1);
                MMA16816(o[nt][0], o[nt][1], o[nt][2], o[nt][3],
                         aPh[4*ks], aPh[4*ks+1], aPh[4*ks+2], aPh[4*ks+3], bl0, bl1);
            }
        }
    }

    s0 += __shfl_xor_sync(0xffffffffu, s0, 1);
    s0 += __shfl_xor_sync(0xffffffffu, s0, 2);
    s1 += __shfl_xor_sync(0xffffffffu, s1, 1);
    s1 += __shfl_xor_sync(0xffffffffu, s1, 2);
    float i0 = 1.f / s0, i1 = 1.f / s1;

    #pragma unroll
    for (int nt = 0; nt < 4; nt++) {
        int dd = nt * 8 + fc2;
        float2 w0 = make_float2(o[nt][0] * i0, o[nt][1] * i0);
        float2 w1 = make_float2(o[nt][2] * i1, o[nt][3] * i1);
        *(float2*)&g_o[((size_t)bh * N_ + qr) * HD_ + dd]     = w0;
        *(float2*)&g_o[((size_t)bh * N_ + qr + 8) * HD_ + dd] = w1;
    }
}

// ============================================================
// K5: output projection. o_s/y_s padded to 257 (conflict-free
// column reads/writes; was 16-way conflicted at stride 256).
// (launch index 4)
// ============================================================
__global__ void __launch_bounds__(256) proj_kernel(
    const float* __restrict__ p1w, const float* __restrict__ p1b,
    const float* __restrict__ p2w, const float* __restrict__ p2b,
    float* __restrict__ out)
{
    __shared__ float o_s[16][C_ + 1];   // padded
    __shared__ u64   w_s2[64][16];      // 8 KB
    __shared__ float y_s[16][C_ + 1];   // padded

    const int tid  = threadIdx.x;
    const int tok0 = blockIdx.x * 16;
    const int b    = tok0 / N_;
    const int n0   = tok0 % N_;

    for (int idx = tid; idx < 16 * C_; idx += 256) {
        int t = idx >> 8, c = idx & 255;
        o_s[t][c] = g_o[(((size_t)b * NH_ + (c >> 5)) * N_ + n0 + t) * HD_ + (c & 31)];
    }
    __syncthreads();

    const float* Ws[2] = {p1w, p2w};
    const float* Bs[2] = {p1b, p2b};

    const int lane = tid & 31;
    const int warp = tid >> 5;
    const int t    = lane & 15;
    const int sub  = lane >> 4;
    const int oc0  = warp * 16 + sub * 8;
    const int p0   = oc0 >> 1;

    for (int m = 0; m < 2; m++) {
        const int half = m;
        const float* W  = Ws[m];
        const float* bb = Bs[m];
        u64 acc[4];
        #pragma unroll
        for (int u = 0; u < 4; u++)
            PACKAB(acc[u], bb[oc0 + 2*u], bb[oc0 + 2*u + 1]);

        for (int ch = 0; ch < 8; ch++) {
            __syncthreads();
            #pragma unroll
            for (int r = 0; r < 4; r++) {
                int idx = r * 256 + tid;      // 0..1023
                int p = idx >> 4, ii = idx & 15;
                float w0 = W[(2*p)     * HALF_ + ch * 16 + ii];
                float w1 = W[(2*p + 1) * HALF_ + ch * 16 + ii];
                PACKAB(w_s2[p][ii], w0, w1);
            }
            __syncthreads();
            #pragma unroll 8
            for (int ii = 0; ii < 16; ii++) {
                u64 xx; PACK2(xx, o_s[t][half * HALF_ + ch * 16 + ii]);
                #pragma unroll
                for (int u = 0; u < 4; u++)
                    FMA2(acc[u], w_s2[p0 + u][ii], xx, acc[u]);
            }
        }
        float o[8];
        #pragma unroll
        for (int u = 0; u < 4; u++) UNPACK2(o[2*u], o[2*u+1], acc[u]);
        #pragma unroll
        for (int u = 0; u < 8; u++) y_s[t][half * HALF_ + oc0 + u] = o[u];
    }
    __syncthreads();

    for (int idx = tid; idx < 16 * C_; idx += 256) {
        int c = idx >> 4, t2 = idx & 15;
        out[((size_t)b * C_ + c) * N_ + n0 + t2] = y_s[t2][c];
    }
}

// ============================================================
extern "C" void kernel_launch(void* const* d_in, const int* in_sizes, int n_in,
                              void* d_out, int out_size)
{
    const float* x    = (const float*)d_in[0];
    const float* q1w  = (const float*)d_in[1];
    const float* q1b  = (const float*)d_in[2];
    const float* q2w  = (const float*)d_in[3];
    const float* q2b  = (const float*)d_in[4];
    const float* k1w  = (const float*)d_in[5];
    const float* k1b  = (const float*)d_in[6];
    const float* k2w  = (const float*)d_in[7];
    const float* k2b  = (const float*)d_in[8];
    const float* v1w  = (const float*)d_in[9];
    const float* v1b  = (const float*)d_in[10];
    const float* v2w  = (const float*)d_in[11];
    const float* v2b  = (const float*)d_in[12];
    const float* p1w  = (const float*)d_in[13];
    const float* p1b  = (const float*)d_in[14];
    const float* p2w  = (const float*)d_in[15];
    const float* p2b  = (const float*)d_in[16];
    const float* ls   = (const float*)d_in[17];
    const float* m1w  = (const float*)d_in[18];
    const float* m1b  = (const float*)d_in[19];
    const float* m2w  = (const float*)d_in[20];
    float* out = (float*)d_out;

    // Order keeps attn_kernel at app-launch index 3 (the ncu slot).
    tab_kernel<<<(TABN_ + 255) / 256, 256>>>(m1w, m1b, m2w);
    bias_kernel<<<dim3(N_, N_ / 256), 256>>>();
    qkv_kernel<<<B_ * N_ / 16, 256>>>(x, q1w, q1b, q2w, q2b,
                                      k1w, k1b, k2w, k2b,
                                      v1w, v1b, v2w, v2b);
    attn_kernel<<<dim3(N_ / 128, BH_), 256>>>(ls);
    proj_kernel<<<B_ * N_ / 16, 256>>>(p1w, p1b, p2w, p2b, out);
}

// round 8
// speedup vs baseline: 2.0542x; 1.1140x over previous
#include <cuda_runtime.h>
#include <cuda_bf16.h>
#include <math.h>
#include <stdint.h>

#define B_    16
#define C_    256
#define N_    1024      // 32*32 tokens
#define NH_   8
#define HD_   32
#define HALF_ 128
#define BH_   (B_*NH_)  // 128
#define TABN_ 3969      // 63*63

typedef unsigned long long u64;
typedef unsigned int u32;

// packed fp32x2 ops (used in qkv/proj GEMMs)
#define FMA2(d,a,b,c) asm("fma.rn.f32x2 %0, %1, %2, %3;" : "=l"(d) : "l"(a), "l"(b), "l"(c))
#define PACK2(d,x)    asm("mov.b64 %0, {%1, %1};"        : "=l"(d) : "f"(x))
#define PACKAB(d,lo,hi) asm("mov.b64 %0, {%1, %2};"      : "=l"(d) : "f"(lo), "f"(hi))
#define UNPACK2(lo,hi,p) asm("mov.b64 {%0, %1}, %2;" : "=f"(lo), "=f"(hi) : "l"(p))

// bf16 mma m16n8k16, fp32 accum
#define MMA16816(d0,d1,d2,d3,a0,a1,a2,a3,b0,b1) \
    asm("mma.sync.aligned.m16n8k16.row.col.f32.bf16.bf16.f32 " \
        "{%0,%1,%2,%3}, {%4,%5,%6,%7}, {%8,%9}, {%0,%1,%2,%3};" \
        : "+f"(d0), "+f"(d1), "+f"(d2), "+f"(d3) \
        : "r"(a0), "r"(a1), "r"(a2), "r"(a3), "r"(b0), "r"(b1))

#define LDSM_X4(r0,r1,r2,r3,addr) \
    asm volatile("ldmatrix.sync.aligned.m8n8.x4.shared.b16 {%0,%1,%2,%3}, [%4];" \
        : "=r"(r0), "=r"(r1), "=r"(r2), "=r"(r3) : "r"(addr))

#define CP_ASYNC16(dst,src) \
    asm volatile("cp.async.cg.shared.global [%0], [%1], 16;" :: "r"(dst), "l"(src))
#define CP_COMMIT() asm volatile("cp.async.commit_group;")
#define CP_WAIT0()  asm volatile("cp.async.wait_group 0;")

__device__ __forceinline__ u32 smem_u32(const void* p) {
    u32 a;
    asm("{ .reg .u64 t; cvta.to.shared.u64 t, %1; cvt.u32.u64 %0, t; }"
        : "=r"(a) : "l"(p));
    return a;
}

// ---- scratch (device globals; no runtime allocation allowed) ----
__device__ __nv_bfloat16 g_qs[BH_*N_*96];   // [qh|ql|qh]  25 MB
__device__ __nv_bfloat16 g_ks[BH_*N_*96];   // [kh|kh|kl]  25 MB
__device__ __nv_bfloat16 g_vt[BH_*64*N_];   // [bh][vh(32)+vl(32)][key] 16 MB
__device__ float g_o[BH_*N_*HD_];           // 16 MB
__device__ float g_tab[TABN_*NH_];          // 127 KB
__device__ float g_biasB[NH_*N_*N_];        // 32 MB, layout [h][query][key]

__device__ __forceinline__ u32 pkh(__nv_bfloat16 a, __nv_bfloat16 b) {
    __nv_bfloat162 t; t.x = a; t.y = b;
    return *(u32*)&t;
}
__device__ __forceinline__ u32 pkf(float a, float b) {
    __nv_bfloat162 t = __floats2bfloat162_rn(a, b);
    return *(u32*)&t;
}

// ============================================================
// K2: CPB table MLP (launch index 0)
// ============================================================
__global__ void __launch_bounds__(256) tab_kernel(
    const float* __restrict__ w1, const float* __restrict__ b1,
    const float* __restrict__ w2)
{
    __shared__ float w1s[256];
    __shared__ float b1s[128];
    __shared__ float w2s[1024];
    int tid = threadIdx.x;
    if (tid < 256) w1s[tid] = w1[tid];
    if (tid < 128) b1s[tid] = b1[tid];
    for (int i = tid; i < 1024; i += 256) w2s[i] = w2[i];
    __syncthreads();

    int p = blockIdx.x * 256 + tid;
    if (p >= TABN_) return;
    int a = p / 63, b = p % 63;
    float t0 = ((float)(a - 31) / 31.0f) * 3.2f;
    float t1 = ((float)(b - 31) / 31.0f) * 3.2f;
    t0 = copysignf(1.f - __expf(-fabsf(t0)), t0);
    t1 = copysignf(1.f - __expf(-fabsf(t1)), t1);

    float acc[NH_];
    #pragma unroll
    for (int h = 0; h < NH_; h++) acc[h] = 0.f;
    for (int k = 0; k < 128; k++) {
        float hv = fmaxf(w1s[2 * k] * t0 + w1s[2 * k + 1] * t1 + b1s[k], 0.f);
        #pragma unroll
        for (int h = 0; h < NH_; h++) acc[h] += w2s[h * 128 + k] * hv;
    }
    #pragma unroll
    for (int h = 0; h < NH_; h++) g_tab[p * NH_ + h] = acc[h];
}

// ============================================================
// K3: expand bias to [h][query][key] (launch index 1)
// ============================================================
__global__ void __launch_bounds__(256) bias_kernel()
{
    int n = blockIdx.x;                       // query
    int m = blockIdx.y * 256 + threadIdx.x;   // key
    int i = n >> 5, j = n & 31;
    int p = m >> 5, q = m & 31;
    int idx = (i - p + 31) * 63 + (j - q + 31);
    const float* t = g_tab + idx * NH_;
    #pragma unroll
    for (int h = 0; h < NH_; h++) {
        float v = 16.f / (1.f + __expf(-t[h]));
        g_biasB[((size_t)h * N_ + n) * N_ + m] = v;
    }
}

// ============================================================
// K0: QKV projection + residual + fused q/k normalization +
// split-bf16 emission. (launch index 2)
// ============================================================
__global__ void __launch_bounds__(256) qkv_kernel(
    const float* __restrict__ x,
    const float* __restrict__ q1w, const float* __restrict__ q1b,
    const float* __restrict__ q2w, const float* __restrict__ q2b,
    const float* __restrict__ k1w, const float* __restrict__ k1b,
    const float* __restrict__ k2w, const float* __restrict__ k2b,
    const float* __restrict__ v1w, const float* __restrict__ v1b,
    const float* __restrict__ v2w, const float* __restrict__ v2b)
{
    __shared__ float x_s[16][C_ + 1];   // padded: conflict-free column reads
    __shared__ u64   w_s2[64][32];      // [oc_pair][ii]
    __shared__ float buf_s[16][264];    // padded

    const int tid  = threadIdx.x;
    const int tok0 = blockIdx.x * 16;
    const int b    = tok0 / N_;
    const int n0   = tok0 % N_;

    #pragma unroll
    for (int r = 0; r < 4; r++) {
        int idx = r * 256 + tid;          // 0..1023 float4 slots
        int c = idx >> 2, t4 = (idx & 3) * 4;
        float4 xv = *(const float4*)&x[(b * C_ + c) * N_ + n0 + t4];
        x_s[t4 + 0][c] = xv.x; x_s[t4 + 1][c] = xv.y;
        x_s[t4 + 2][c] = xv.z; x_s[t4 + 3][c] = xv.w;
    }
    __syncthreads();

    const float* Ws[6] = {q1w, q2w, k1w, k2w, v1w, v2w};
    const float* Bs[6] = {q1b, q2b, k1b, k2b, v1b, v2b};

    const int lane  = tid & 31;
    const int warp  = tid >> 5;
    const int t     = lane & 15;
    const int sub   = lane >> 4;
    const int oc0   = warp * 16 + sub * 8;
    const int p0    = oc0 >> 1;

    for (int pair = 0; pair < 3; pair++) {
        for (int half = 0; half < 2; half++) {
            const int m = pair * 2 + half;
            const float* W  = Ws[m];
            const float* bb = Bs[m];

            u64 acc[4];
            #pragma unroll
            for (int u = 0; u < 4; u++) {
                float r0 = x_s[t][half * HALF_ + oc0 + 2*u]     + bb[oc0 + 2*u];
                float r1 = x_s[t][half * HALF_ + oc0 + 2*u + 1] + bb[oc0 + 2*u + 1];
                PACKAB(acc[u], r0, r1);
            }

            for (int ch = 0; ch < 4; ch++) {
                __syncthreads();
                #pragma unroll
                for (int r = 0; r < 8; r++) {
                    int idx = r * 256 + tid;     // 0..2047
                    int p = idx >> 5, ii = idx & 31;
                    float w0 = W[(2*p)     * HALF_ + ch * 32 + ii];
                    float w1 = W[(2*p + 1) * HALF_ + ch * 32 + ii];
                    PACKAB(w_s2[p][ii], w0, w1);
                }
                __syncthreads();
                #pragma unroll 8
                for (int ii = 0; ii < 32; ii++) {
                    u64 xx; PACK2(xx, x_s[t][half * HALF_ + ch * 32 + ii]);
                    #pragma unroll
                    for (int u = 0; u < 4; u++)
                        FMA2(acc[u], w_s2[p0 + u][ii], xx, acc[u]);
                }
            }

            float o[8];
            #pragma unroll
            for (int u = 0; u < 4; u++) UNPACK2(o[2*u], o[2*u+1], acc[u]);
            #pragma unroll
            for (int u = 0; u < 8; u++)
                buf_s[t][half * HALF_ + oc0 + u] = o[u];
        }

        __syncthreads();
        if (tid < 128) {
            const int t2   = tid >> 3;
            const int head = tid & 7;
            const int bh   = b * NH_ + head;
            const int nn   = n0 + t2;
            float vals[32];
            float s = 0.f;
            #pragma unroll
            for (int i = 0; i < 8; i++) {
                float4 r = *(float4*)&buf_s[t2][head * 32 + i * 4];
                vals[4*i+0] = r.x; vals[4*i+1] = r.y;
                vals[4*i+2] = r.z; vals[4*i+3] = r.w;
                s += r.x*r.x + r.y*r.y + r.z*r.z + r.w*r.w;
            }
            if (pair < 2) {
                float inv = 1.f / fmaxf(sqrtf(s), 1e-12f);
                #pragma unroll
                for (int i = 0; i < 32; i++) vals[i] *= inv;
                u32 hseg[16], lseg[16];
                #pragma unroll
                for (int j = 0; j < 16; j++) {
                    __nv_bfloat16 ha = __float2bfloat16(vals[2*j]);
                    __nv_bfloat16 hb = __float2bfloat16(vals[2*j+1]);
                    float la = vals[2*j]   - __bfloat162float(ha);
                    float lb = vals[2*j+1] - __bfloat162float(hb);
                    hseg[j] = pkh(ha, hb);
                    lseg[j] = pkf(la, lb);
                }
                u32* dst = (u32*)((pair == 0 ? g_qs : g_ks)
                                  + ((size_t)bh * N_ + nn) * 96);
                if (pair == 0) {        // [qh | ql | qh]
                    #pragma unroll
                    for (int j = 0; j < 16; j++) {
                        dst[j] = hseg[j]; dst[16+j] = lseg[j]; dst[32+j] = hseg[j];
                    }
                } else {                // [kh | kh | kl]
                    #pragma unroll
                    for (int j = 0; j < 16; j++) {
                        dst[j] = hseg[j]; dst[16+j] = hseg[j]; dst[32+j] = lseg[j];
                    }
                }
            } else {
                #pragma unroll
                for (int f = 0; f < 32; f++) {
                    __nv_bfloat16 hv = __float2bfloat16(vals[f]);
                    g_vt[((size_t)bh * 64 + f) * N_ + nn] = hv;
                    g_vt[((size_t)bh * 64 + 32 + f) * N_ + nn] =
                        __float2bfloat16(vals[f] - __bfloat162float(hv));
                }
            }
        }
        __syncthreads();
    }
}

// ============================================================
// K4: attention via bf16 mma.sync + ldmatrix.x4 B-operands +
// cp.async double-buffered K/V tiles. (launch index 3)
// ============================================================
__global__ void __launch_bounds__(256, 2) attn_kernel(const float* __restrict__ logit_scale)
{
    __shared__ __align__(16) __nv_bfloat16 ks_s[2][64][104];  // 2 x 13 KB
    __shared__ __align__(16) __nv_bfloat16 vt_s[2][64][72];   // 2 x 9 KB

    const int tid  = threadIdx.x;
    const int lane = tid & 31;
    const int w    = tid >> 5;
    const int bh   = blockIdx.y;
    const int h    = bh & 7;
    const int q0   = blockIdx.x * 128;
    const int qr   = q0 + w * 16 + (lane >> 2);   // row r0 (r1 = qr+8)
    const int fc2  = 2 * (lane & 3);

    // Q A-fragments: 6 ksteps x 4 regs (K=96 split layout)
    u32 aQ[6][4];
    {
        const __nv_bfloat16* qb = g_qs + ((size_t)bh * N_ + qr) * 96;
        #pragma unroll
        for (int ks = 0; ks < 6; ks++) {
            int f = fc2 + 16 * ks;
            aQ[ks][0] = *(const u32*)(qb + f);
            aQ[ks][1] = *(const u32*)(qb + 8 * 96 + f);
            aQ[ks][2] = *(const u32*)(qb + f + 8);
            aQ[ks][3] = *(const u32*)(qb + 8 * 96 + f + 8);
        }
    }

    const float scale = __expf(fminf(logit_scale[h], 4.6051702f)); // log(100)
    const float M = scale + 16.0f;

    float o[4][4];
    #pragma unroll
    for (int i = 0; i < 4; i++)
        #pragma unroll
        for (int j = 0; j < 4; j++) o[i][j] = 0.f;
    float s0 = 0.f, s1 = 0.f;

    const float* bias0 = g_biasB + ((size_t)h * N_ + qr) * N_;
    const float* bias1 = bias0 + (size_t)8 * N_;

    const u32 ks0 = smem_u32(&ks_s[0][0][0]);
    const u32 vt0 = smem_u32(&vt_s[0][0][0]);
    const u32 KSB = 64 * 104 * 2;   // 13312 bytes per K buffer
    const u32 VTB = 64 * 72 * 2;    // 9216 bytes per V buffer

    // lane-fixed ldmatrix offsets (x4: lanes0-7 m0, 8-15 m1, 16-23 m2, 24-31 m3)
    const u32 lmK = (u32)(((((lane >> 4) & 1) * 8 + (lane & 7)) * 104
                           + ((lane >> 3) & 1) * 8) * 2);
    const u32 lmV = (u32)(((((lane >> 4) & 1) * 32 + (lane & 7)) * 72
                           + ((lane >> 3) & 1) * 8) * 2);

    const char* kgbase = (const char*)(g_ks + (size_t)bh * N_ * 96);
    const char* vgbase = (const char*)(g_vt + (size_t)bh * 64 * N_);

    // stage tile kt into buffer bf
    auto stage = [&](int kt, int bf) {
        const char* src = kgbase + (size_t)kt * 64 * 192;   // 96 bf16 = 192B/row
        u32 dst = ks0 + bf * KSB;
        #pragma unroll
        for (int i = 0; i < 3; i++) {
            int idx = i * 256 + tid;          // 0..767
            int key = idx / 12, seg = idx % 12;
            CP_ASYNC16(dst + (key * 104 + seg * 8) * 2, src + key * 192 + seg * 16);
        }
        const char* vs = vgbase + (size_t)kt * 64 * 2;
        u32 vdst = vt0 + bf * VTB;
        #pragma unroll
        for (int i = 0; i < 2; i++) {
            int idx = i * 256 + tid;          // 0..511
            int f = idx / 8, seg = idx % 8;
            CP_ASYNC16(vdst + (f * 72 + seg * 8) * 2, vs + (size_t)f * N_ * 2 + seg * 16);
        }
        CP_COMMIT();
    };

    stage(0, 0);

    for (int kt = 0; kt < 16; kt++) {
        const int buf = kt & 1;
        CP_WAIT0();
        __syncthreads();
        if (kt < 15) stage(kt + 1, buf ^ 1);

        const u32 kbase = ks0 + buf * KSB;
        const u32 vbase = vt0 + buf * VTB;

        // ---- QK^T: S tile (16 q x 64 keys per warp), K=96 ----
        float c[8][4];
        #pragma unroll
        for (int nt = 0; nt < 8; nt++) {
            c[nt][0] = 0.f; c[nt][1] = 0.f; c[nt][2] = 0.f; c[nt][3] = 0.f;
        }
        #pragma unroll
        for (int ks = 0; ks < 6; ks++) {
            #pragma unroll
            for (int ntp = 0; ntp < 4; ntp++) {
                u32 b00, b01, b10, b11;
                LDSM_X4(b00, b01, b10, b11,
                        kbase + lmK + (u32)((ntp * 16 * 104 + 16 * ks) * 2));
                MMA16816(c[2*ntp][0], c[2*ntp][1], c[2*ntp][2], c[2*ntp][3],
                         aQ[ks][0], aQ[ks][1], aQ[ks][2], aQ[ks][3], b00, b01);
                MMA16816(c[2*ntp+1][0], c[2*ntp+1][1], c[2*ntp+1][2], c[2*ntp+1][3],
                         aQ[ks][0], aQ[ks][1], aQ[ks][2], aQ[ks][3], b10, b11);
            }
        }

        // ---- softmax (constant shift) + split-pack P ----
        u32 aPh[16], aPl[16];
        #pragma unroll
        for (int nt = 0; nt < 8; nt++) {
            int kg = kt * 64 + nt * 8 + fc2;
            float2 bb0 = *(const float2*)(bias0 + kg);
            float2 bb1 = *(const float2*)(bias1 + kg);
            float pv0 = __expf(fmaf(c[nt][0], scale, bb0.x - M));
            float pv1 = __expf(fmaf(c[nt][1], scale, bb0.y - M));
            float pv2 = __expf(fmaf(c[nt][2], scale, bb1.x - M));
            float pv3 = __expf(fmaf(c[nt][3], scale, bb1.y - M));
            s0 += pv0 + pv1;
            s1 += pv2 + pv3;
            __nv_bfloat16 h0 = __float2bfloat16(pv0);
            __nv_bfloat16 h1 = __float2bfloat16(pv1);
            __nv_bfloat16 h2 = __float2bfloat16(pv2);
            __nv_bfloat16 h3 = __float2bfloat16(pv3);
            aPh[nt * 2]     = pkh(h0, h1);
            aPh[nt * 2 + 1] = pkh(h2, h3);
            aPl[nt * 2]     = pkf(pv0 - __bfloat162float(h0), pv1 - __bfloat162float(h1));
            aPl[nt * 2 + 1] = pkf(pv2 - __bfloat162float(h2), pv3 - __bfloat162float(h3));
        }

        // ---- P·V: O += ph*vh + pl*vh + ph*vl ----
        #pragma unroll
        for (int ks = 0; ks < 4; ks++) {
            #pragma unroll
            for (int nt = 0; nt < 4; nt++) {
                u32 bh0, bh1, bl0, bl1;
                LDSM_X4(bh0, bh1, bl0, bl1,
                        vbase + lmV + (u32)((nt * 8 * 72 + 16 * ks) * 2));
                MMA16816(o[nt][0], o[nt][1], o[nt][2], o[nt][3],
                         aPh[4*ks], aPh[4*ks+1], aPh[4*ks+2], aPh[4*ks+3], bh0, bh1);
                MMA16816(o[nt][0], o[nt][1], o[nt][2], o[nt][3],
                         aPl[4*ks], aPl[4*ks+1], aPl[4*ks+2], aPl[4*ks+3], bh0, bh1);
                MMA16816(o[nt][0], o[nt][1], o[nt][2], o[nt][3],
                         aPh[4*ks], aPh[4*ks+1], aPh[4*ks+2], aPh[4*ks+3], bl0, bl1);
            }
        }
    }

    s0 += __shfl_xor_sync(0xffffffffu, s0, 1);
    s0 += __shfl_xor_sync(0xffffffffu, s0, 2);
    s1 += __shfl_xor_sync(0xffffffffu, s1, 1);
    s1 += __shfl_xor_sync(0xffffffffu, s1, 2);
    float i0 = 1.f / s0, i1 = 1.f / s1;

    #pragma unroll
    for (int nt = 0; nt < 4; nt++) {
        int dd = nt * 8 + fc2;
        float2 w0 = make_float2(o[nt][0] * i0, o[nt][1] * i0);
        float2 w1 = make_float2(o[nt][2] * i1, o[nt][3] * i1);
        *(float2*)&g_o[((size_t)bh * N_ + qr) * HD_ + dd]     = w0;
        *(float2*)&g_o[((size_t)bh * N_ + qr + 8) * HD_ + dd] = w1;
    }
}

// ============================================================
// K5: output projection (padded smem, f32x2 inner). (launch index 4)
// ============================================================
__global__ void __launch_bounds__(256) proj_kernel(
    const float* __restrict__ p1w, const float* __restrict__ p1b,
    const float* __restrict__ p2w, const float* __restrict__ p2b,
    float* __restrict__ out)
{
    __shared__ float o_s[16][C_ + 1];   // padded
    __shared__ u64   w_s2[64][16];
    __shared__ float y_s[16][C_ + 1];   // padded

    const int tid  = threadIdx.x;
    const int tok0 = blockIdx.x * 16;
    const int b    = tok0 / N_;
    const int n0   = tok0 % N_;

    for (int idx = tid; idx < 16 * C_; idx += 256) {
        int t = idx >> 8, c = idx & 255;
        o_s[t][c] = g_o[(((size_t)b * NH_ + (c >> 5)) * N_ + n0 + t) * HD_ + (c & 31)];
    }
    __syncthreads();

    const float* Ws[2] = {p1w, p2w};
    const float* Bs[2] = {p1b, p2b};

    const int lane = tid & 31;
    const int warp = tid >> 5;
    const int t    = lane & 15;
    const int sub  = lane >> 4;
    const int oc0  = warp * 16 + sub * 8;
    const int p0   = oc0 >> 1;

    for (int m = 0; m < 2; m++) {
        const int half = m;
        const float* W  = Ws[m];
        const float* bb = Bs[m];
        u64 acc[4];
        #pragma unroll
        for (int u = 0; u < 4; u++)
            PACKAB(acc[u], bb[oc0 + 2*u], bb[oc0 + 2*u + 1]);

        for (int ch = 0; ch < 8; ch++) {
            __syncthreads();
            #pragma unroll
            for (int r = 0; r < 4; r++) {
                int idx = r * 256 + tid;      // 0..1023
                int p = idx >> 4, ii = idx & 15;
                float w0 = W[(2*p)     * HALF_ + ch * 16 + ii];
                float w1 = W[(2*p + 1) * HALF_ + ch * 16 + ii];
                PACKAB(w_s2[p][ii], w0, w1);
            }
            __syncthreads();
            #pragma unroll 8
            for (int ii = 0; ii < 16; ii++) {
                u64 xx; PACK2(xx, o_s[t][half * HALF_ + ch * 16 + ii]);
                #pragma unroll
                for (int u = 0; u < 4; u++)
                    FMA2(acc[u], w_s2[p0 + u][ii], xx, acc[u]);
            }
        }
        float o[8];
        #pragma unroll
        for (int u = 0; u < 4; u++) UNPACK2(o[2*u], o[2*u+1], acc[u]);
        #pragma unroll
        for (int u = 0; u < 8; u++) y_s[t][half * HALF_ + oc0 + u] = o[u];
    }
    __syncthreads();

    for (int idx = tid; idx < 16 * C_; idx += 256) {
        int c = idx >> 4, t2 = idx & 15;
        out[((size_t)b * C_ + c) * N_ + n0 + t2] = y_s[t2][c];
    }
}

// ============================================================
extern "C" void kernel_launch(void* const* d_in, const int* in_sizes, int n_in,
                              void* d_out, int out_size)
{
    const float* x    = (const float*)d_in[0];
    const float* q1w  = (const float*)d_in[1];
    const float* q1b  = (const float*)d_in[2];
    const float* q2w  = (const float*)d_in[3];
    const float* q2b  = (const float*)d_in[4];
    const float* k1w  = (const float*)d_in[5];
    const float* k1b  = (const float*)d_in[6];
    const float* k2w  = (const float*)d_in[7];
    const float* k2b  = (const float*)d_in[8];
    const float* v1w  = (const float*)d_in[9];
    const float* v1b  = (const float*)d_in[10];
    const float* v2w  = (const float*)d_in[11];
    const float* v2b  = (const float*)d_in[12];
    const float* p1w  = (const float*)d_in[13];
    const float* p1b  = (const float*)d_in[14];
    const float* p2w  = (const float*)d_in[15];
    const float* p2b  = (const float*)d_in[16];
    const float* ls   = (const float*)d_in[17];
    const float* m1w  = (const float*)d_in[18];
    const float* m1b  = (const float*)d_in[19];
    const float* m2w  = (const float*)d_in[20];
    float* out = (float*)d_out;

    // Order keeps attn_kernel at app-launch index 3 (the ncu slot).
    tab_kernel<<<(TABN_ + 255) / 256, 256>>>(m1w, m1b, m2w);
    bias_kernel<<<dim3(N_, N_ / 256), 256>>>();
    qkv_kernel<<<B_ * N_ / 16, 256>>>(x, q1w, q1b, q2w, q2b,
                                      k1w, k1b, k2w, k2b,
                                      v1w, v1b, v2w, v2b);
    attn_kernel<<<dim3(N_ / 128, BH_), 256>>>(ls);
    proj_kernel<<<B_ * N_ / 16, 256>>>(p1w, p1b, p2w, p2b, out);
}

// round 9
// speedup vs baseline: 2.8926x; 1.4081x over previous
#include <cuda_runtime.h>
#include <cuda_bf16.h>
#include <math.h>
#include <stdint.h>

#define B_    16
#define C_    256
#define N_    1024      // 32*32 tokens
#define NH_   8
#define HD_   32
#define HALF_ 128
#define BH_   (B_*NH_)  // 128
#define TABN_ 3969      // 63*63

typedef unsigned long long u64;
typedef unsigned int u32;

// packed fp32x2 ops (proj GEMM)
#define FMA2(d,a,b,c) asm("fma.rn.f32x2 %0, %1, %2, %3;" : "=l"(d) : "l"(a), "l"(b), "l"(c))
#define PACK2(d,x)    asm("mov.b64 %0, {%1, %1};"        : "=l"(d) : "f"(x))
#define PACKAB(d,lo,hi) asm("mov.b64 %0, {%1, %2};"      : "=l"(d) : "f"(lo), "f"(hi))
#define UNPACK2(lo,hi,p) asm("mov.b64 {%0, %1}, %2;" : "=f"(lo), "=f"(hi) : "l"(p))

// bf16 mma m16n8k16, fp32 accum
#define MMA16816(d0,d1,d2,d3,a0,a1,a2,a3,b0,b1) \
    asm("mma.sync.aligned.m16n8k16.row.col.f32.bf16.bf16.f32 " \
        "{%0,%1,%2,%3}, {%4,%5,%6,%7}, {%8,%9}, {%0,%1,%2,%3};" \
        : "+f"(d0), "+f"(d1), "+f"(d2), "+f"(d3) \
        : "r"(a0), "r"(a1), "r"(a2), "r"(a3), "r"(b0), "r"(b1))

#define LDSM_X4(r0,r1,r2,r3,addr) \
    asm volatile("ldmatrix.sync.aligned.m8n8.x4.shared.b16 {%0,%1,%2,%3}, [%4];" \
        : "=r"(r0), "=r"(r1), "=r"(r2), "=r"(r3) : "r"(addr))

#define LDSM_X4_T(r0,r1,r2,r3,addr) \
    asm volatile("ldmatrix.sync.aligned.m8n8.x4.trans.shared.b16 {%0,%1,%2,%3}, [%4];" \
        : "=r"(r0), "=r"(r1), "=r"(r2), "=r"(r3) : "r"(addr))

#define CP_ASYNC16(dst,src) \
    asm volatile("cp.async.cg.shared.global [%0], [%1], 16;" :: "r"(dst), "l"(src))
#define CP_COMMIT() asm volatile("cp.async.commit_group;")
#define CP_WAIT0()  asm volatile("cp.async.wait_group 0;")

__device__ __forceinline__ u32 smem_u32(const void* p) {
    u32 a;
    asm("{ .reg .u64 t; cvta.to.shared.u64 t, %1; cvt.u32.u64 %0, t; }"
        : "=r"(a) : "l"(p));
    return a;
}

// ---- scratch (device globals; no runtime allocation allowed) ----
__device__ float g_q[B_*C_*N_];             // 16 MB, [b][c][tok] (pre-norm, +residual+bias)
__device__ float g_k[B_*C_*N_];             // 16 MB
__device__ float g_v[B_*C_*N_];             // 16 MB
__device__ __nv_bfloat16 g_wext[6*128*384]; // K-extended split weights [wh|wl|wh]
__device__ __nv_bfloat16 g_qs[BH_*N_*96];   // [qh|ql|qh]  25 MB
__device__ __nv_bfloat16 g_ks[BH_*N_*96];   // [kh|kh|kl]  25 MB
__device__ __nv_bfloat16 g_vt[BH_*64*N_];   // [bh][vh(32)+vl(32)][key] 16 MB
__device__ float g_o[BH_*N_*HD_];           // 16 MB
__device__ float g_tab[TABN_*NH_];          // 127 KB
__device__ float g_biasB[NH_*N_*N_];        // 32 MB, layout [h][query][key]

__device__ __forceinline__ u32 pkh(__nv_bfloat16 a, __nv_bfloat16 b) {
    __nv_bfloat162 t; t.x = a; t.y = b;
    return *(u32*)&t;
}
__device__ __forceinline__ u32 pkf(float a, float b) {
    __nv_bfloat162 t = __floats2bfloat162_rn(a, b);
    return *(u32*)&t;
}

// ============================================================
// K_wext: precompute split weights, K-extended [wh | wl | wh].
// (launch index 0)
// ============================================================
__global__ void __launch_bounds__(256) wext_kernel(
    const float* __restrict__ q1w, const float* __restrict__ q2w,
    const float* __restrict__ k1w, const float* __restrict__ k2w,
    const float* __restrict__ v1w, const float* __restrict__ v2w)
{
    const float* Ws[6] = {q1w, q2w, k1w, k2w, v1w, v2w};
    int g = blockIdx.x;
    int e = blockIdx.y * 256 + threadIdx.x;      // 0..16383
    float v = Ws[g][e];
    int oc = e >> 7, ic = e & 127;
    __nv_bfloat16 hh = __float2bfloat16(v);
    __nv_bfloat16 ll = __float2bfloat16(v - __bfloat162float(hh));
    __nv_bfloat16* o = g_wext + ((size_t)(g * 128 + oc)) * 384;
    o[ic] = hh; o[128 + ic] = ll; o[256 + ic] = hh;
}

// ============================================================
// K2: CPB table MLP (launch index 1)
// ============================================================
__global__ void __launch_bounds__(256) tab_kernel(
    const float* __restrict__ w1, const float* __restrict__ b1,
    const float* __restrict__ w2)
{
    __shared__ float w1s[256];
    __shared__ float b1s[128];
    __shared__ float w2s[1024];
    int tid = threadIdx.x;
    if (tid < 256) w1s[tid] = w1[tid];
    if (tid < 128) b1s[tid] = b1[tid];
    for (int i = tid; i < 1024; i += 256) w2s[i] = w2[i];
    __syncthreads();

    int p = blockIdx.x * 256 + tid;
    if (p >= TABN_) return;
    int a = p / 63, b = p % 63;
    float t0 = ((float)(a - 31) / 31.0f) * 3.2f;
    float t1 = ((float)(b - 31) / 31.0f) * 3.2f;
    t0 = copysignf(1.f - __expf(-fabsf(t0)), t0);
    t1 = copysignf(1.f - __expf(-fabsf(t1)), t1);

    float acc[NH_];
    #pragma unroll
    for (int h = 0; h < NH_; h++) acc[h] = 0.f;
    for (int k = 0; k < 128; k++) {
        float hv = fmaxf(w1s[2 * k] * t0 + w1s[2 * k + 1] * t1 + b1s[k], 0.f);
        #pragma unroll
        for (int h = 0; h < NH_; h++) acc[h] += w2s[h * 128 + k] * hv;
    }
    #pragma unroll
    for (int h = 0; h < NH_; h++) g_tab[p * NH_ + h] = acc[h];
}

// ============================================================
// K3: expand bias to [h][query][key] (launch index 2)
// ============================================================
__global__ void __launch_bounds__(256) bias_kernel()
{
    int n = blockIdx.x;                       // query
    int m = blockIdx.y * 256 + threadIdx.x;   // key
    int i = n >> 5, j = n & 31;
    int p = m >> 5, q = m & 31;
    int idx = (i - p + 31) * 63 + (j - q + 31);
    const float* t = g_tab + idx * NH_;
    #pragma unroll
    for (int h = 0; h < NH_; h++) {
        float v = 16.f / (1.f + __expf(-t[h]));
        g_biasB[((size_t)h * N_ + n) * N_ + m] = v;
    }
}

// ============================================================
// K_qkvgemm: q/k/v projections via bf16 mma (3-term split, K=384).
// C[oc][tok] = W[oc][ch] · x[ch][tok]; x is NCHW so B is already
// channel-major — staged as bf16 splits, fragments via ldmatrix.trans.
// Epilogue adds bias + residual, writes fp32 [b][c][tok].
// grid (16 token-tiles of 64, 16 b), 256 threads. (launch index 3 — ncu slot)
// ============================================================
__global__ void __launch_bounds__(256) qkvgemm_kernel(
    const float* __restrict__ x,
    const float* __restrict__ q1b, const float* __restrict__ q2b,
    const float* __restrict__ k1b, const float* __restrict__ k2b,
    const float* __restrict__ v1b, const float* __restrict__ v2b)
{
    __shared__ __align__(16) __nv_bfloat16 xh_s[128][72];   // [ch][tok], pad 72
    __shared__ __align__(16) __nv_bfloat16 xl_s[128][72];

    const int tid  = threadIdx.x;
    const int lane = tid & 31;
    const int w    = tid >> 5;
    const int b    = blockIdx.y;
    const int tok0 = blockIdx.x * 64;
    const int r0   = w * 16 + (lane >> 2);   // A row (oc) for a0/a2; a1/a3 = r0+8
    const int fc2  = 2 * (lane & 3);

    const u32 xh0 = smem_u32(&xh_s[0][0]);
    const u32 xl0 = smem_u32(&xl_s[0][0]);
    // ldmatrix.x4.trans lane offset: groups (lanes/8) -> (k0,n0),(k8,n0),(k0,n8),(k8,n8)
    const u32 lmoff = (u32)((((lane & 7) + ((lane >> 3) & 1) * 8) * 144)
                            + ((lane >> 4) & 1) * 16);

    const float* Bss[6] = {q1b, q2b, k1b, k2b, v1b, v2b};
    float* Outs[3] = {g_q, g_k, g_v};

    for (int half = 0; half < 2; half++) {
        __syncthreads();
        // stage x half as bf16 splits: 128 ch x 64 tok
        #pragma unroll
        for (int r = 0; r < 8; r++) {
            int idx = r * 256 + tid;             // 0..2047
            int ch = idx >> 4, t4 = (idx & 15) * 4;
            float4 xv = *(const float4*)&x[((size_t)(b * 256 + half * 128 + ch) << 10) + tok0 + t4];
            __nv_bfloat16 h0 = __float2bfloat16(xv.x), h1 = __float2bfloat16(xv.y);
            __nv_bfloat16 h2 = __float2bfloat16(xv.z), h3 = __float2bfloat16(xv.w);
            uint2 hw = make_uint2(pkh(h0, h1), pkh(h2, h3));
            uint2 lw = make_uint2(pkf(xv.x - __bfloat162float(h0), xv.y - __bfloat162float(h1)),
                                  pkf(xv.z - __bfloat162float(h2), xv.w - __bfloat162float(h3)));
            *(uint2*)&xh_s[ch][t4] = hw;
            *(uint2*)&xl_s[ch][t4] = lw;
        }
        __syncthreads();

        for (int g = 0; g < 3; g++) {
            const int m = g * 2 + half;
            const __nv_bfloat16* wrow = g_wext + ((size_t)(m * 128 + r0)) * 384 + fc2;

            float c[8][4];
            #pragma unroll
            for (int i = 0; i < 8; i++) { c[i][0] = c[i][1] = c[i][2] = c[i][3] = 0.f; }

            #pragma unroll 4
            for (int ks = 0; ks < 24; ks++) {
                // A fragments from K-extended weights (L2-resident)
                u32 a0 = *(const u32*)(wrow + ks * 16);
                u32 a1 = *(const u32*)(wrow + 8 * 384 + ks * 16);
                u32 a2 = *(const u32*)(wrow + ks * 16 + 8);
                u32 a3 = *(const u32*)(wrow + 8 * 384 + ks * 16 + 8);
                // B: ks0-7 xh, ks8-15 xh, ks16-23 xl (terms wh*xh + wl*xh + wh*xl)
                u32 bb = ((ks < 16) ? xh0 : xl0) + (u32)((ks & 7) * 16 * 144) + lmoff;
                #pragma unroll
                for (int nt = 0; nt < 4; nt++) {
                    u32 f0, f1, f2, f3;
                    LDSM_X4_T(f0, f1, f2, f3, bb + nt * 32);
                    MMA16816(c[2*nt][0], c[2*nt][1], c[2*nt][2], c[2*nt][3],
                             a0, a1, a2, a3, f0, f1);
                    MMA16816(c[2*nt+1][0], c[2*nt+1][1], c[2*nt+1][2], c[2*nt+1][3],
                             a0, a1, a2, a3, f2, f3);
                }
            }

            // epilogue: + bias + residual, store fp32 [b][c][tok]
            float bb0 = __ldg(&Bss[m][r0]);
            float bb1 = __ldg(&Bss[m][r0 + 8]);
            const float* xr = x + ((size_t)(b * 256 + half * 128) << 10);
            float* op = Outs[g] + ((size_t)(b * 256 + half * 128) << 10);
            #pragma unroll
            for (int n8 = 0; n8 < 8; n8++) {
                int tok = tok0 + n8 * 8 + fc2;
                float2 rx0 = *(const float2*)&xr[((size_t)r0 << 10) + tok];
                float2 rx1 = *(const float2*)&xr[((size_t)(r0 + 8) << 10) + tok];
                float2 o0 = make_float2(c[n8][0] + rx0.x + bb0, c[n8][1] + rx0.y + bb0);
                float2 o1 = make_float2(c[n8][2] + rx1.x + bb1, c[n8][3] + rx1.y + bb1);
                *(float2*)&op[((size_t)r0 << 10) + tok] = o0;
                *(float2*)&op[((size_t)(r0 + 8) << 10) + tok] = o1;
            }
        }
    }
}

// ============================================================
// K_normsplit: normalize q/k per (token, head) and emit split-bf16
// K-extended rows (q: [qh|ql|qh], k: [kh|kh|kl]).
// grid (8 tok-chunks of 128, 128 bh, 2 qk), 128 threads. (launch index 4)
// ============================================================
__global__ void __launch_bounds__(128) normsplit_kernel()
{
    __shared__ float xs[32][129];
    __shared__ u32 os[128][49];

    const int tid = threadIdx.x;
    const int chunk = blockIdx.x, bh = blockIdx.y, qk = blockIdx.z;
    const int b = bh >> 3, h = bh & 7;
    const int tok0 = chunk * 128;
    const float* src = (qk ? g_k : g_q) + ((size_t)(b * 256 + h * 32) << 10) + tok0;

    #pragma unroll
    for (int r = 0; r < 8; r++) {
        int idx = r * 128 + tid;          // 0..1023 float4
        int ch = idx >> 5, t4 = (idx & 31) * 4;
        float4 v = *(const float4*)&src[((size_t)ch << 10) + t4];
        xs[ch][t4] = v.x; xs[ch][t4+1] = v.y; xs[ch][t4+2] = v.z; xs[ch][t4+3] = v.w;
    }
    __syncthreads();

    float vals[32]; float s = 0.f;
    #pragma unroll
    for (int ch = 0; ch < 32; ch++) { vals[ch] = xs[ch][tid]; s += vals[ch] * vals[ch]; }
    float inv = 1.f / fmaxf(sqrtf(s), 1e-12f);

    #pragma unroll
    for (int j = 0; j < 16; j++) {
        float v0 = vals[2*j] * inv, v1 = vals[2*j+1] * inv;
        __nv_bfloat16 h0 = __float2bfloat16(v0), h1 = __float2bfloat16(v1);
        u32 hh = pkh(h0, h1);
        u32 ll = pkf(v0 - __bfloat162float(h0), v1 - __bfloat162float(h1));
        if (qk == 0) { os[tid][j] = hh; os[tid][16+j] = ll; os[tid][32+j] = hh; }
        else         { os[tid][j] = hh; os[tid][16+j] = hh; os[tid][32+j] = ll; }
    }
    __syncthreads();

    __nv_bfloat16* dst = (qk ? g_ks : g_qs) + ((size_t)bh * N_ + tok0) * 96;
    #pragma unroll
    for (int r = 0; r < 12; r++) {
        int idx = r * 128 + tid;          // 0..1535 float4
        int row = idx / 12, seg = idx % 12;
        uint4 v = make_uint4(os[row][seg*4], os[row][seg*4+1],
                             os[row][seg*4+2], os[row][seg*4+3]);
        *(uint4*)(dst + (size_t)row * 96 + seg * 8) = v;
    }
}

// ============================================================
// K_vsplit: v [b][c][tok] -> g_vt [bh][vh(32)|vl(32)][tok].
// grid 4096 (one channel row), 256 threads. (launch index 5)
// ============================================================
__global__ void __launch_bounds__(256) vsplit_kernel()
{
    const int row = blockIdx.x;            // b*256 + c
    const int b = row >> 8, c = row & 255;
    const int h = c >> 5, d = c & 31;
    const float* src = g_v + ((size_t)row << 10);
    __nv_bfloat16* dh = g_vt + (((size_t)(b * 8 + h)) * 64 + d) * 1024;
    __nv_bfloat16* dl = dh + 32 * 1024;
    int t4 = threadIdx.x * 4;
    float4 v = *(const float4*)&src[t4];
    __nv_bfloat16 h0 = __float2bfloat16(v.x), h1 = __float2bfloat16(v.y);
    __nv_bfloat16 h2 = __float2bfloat16(v.z), h3 = __float2bfloat16(v.w);
    uint2 hw = make_uint2(pkh(h0, h1), pkh(h2, h3));
    uint2 lw = make_uint2(pkf(v.x - __bfloat162float(h0), v.y - __bfloat162float(h1)),
                          pkf(v.z - __bfloat162float(h2), v.w - __bfloat162float(h3)));
    *(uint2*)&dh[t4] = hw;
    *(uint2*)&dl[t4] = lw;
}

// ============================================================
// K4: attention via bf16 mma.sync + ldmatrix.x4 B-operands +
// cp.async double-buffered K/V tiles. (launch index 6)
// ============================================================
__global__ void __launch_bounds__(256, 2) attn_kernel(const float* __restrict__ logit_scale)
{
    __shared__ __align__(16) __nv_bfloat16 ks_s[2][64][104];
    __shared__ __align__(16) __nv_bfloat16 vt_s[2][64][72];

    const int tid  = threadIdx.x;
    const int lane = tid & 31;
    const int w    = tid >> 5;
    const int bh   = blockIdx.y;
    const int h    = bh & 7;
    const int q0   = blockIdx.x * 128;
    const int qr   = q0 + w * 16 + (lane >> 2);
    const int fc2  = 2 * (lane & 3);

    u32 aQ[6][4];
    {
        const __nv_bfloat16* qb = g_qs + ((size_t)bh * N_ + qr) * 96;
        #pragma unroll
        for (int ks = 0; ks < 6; ks++) {
            int f = fc2 + 16 * ks;
            aQ[ks][0] = *(const u32*)(qb + f);
            aQ[ks][1] = *(const u32*)(qb + 8 * 96 + f);
            aQ[ks][2] = *(const u32*)(qb + f + 8);
            aQ[ks][3] = *(const u32*)(qb + 8 * 96 + f + 8);
        }
    }

    const float scale = __expf(fminf(logit_scale[h], 4.6051702f)); // log(100)
    const float M = scale + 16.0f;

    float o[4][4];
    #pragma unroll
    for (int i = 0; i < 4; i++)
        #pragma unroll
        for (int j = 0; j < 4; j++) o[i][j] = 0.f;
    float s0 = 0.f, s1 = 0.f;

    const float* bias0 = g_biasB + ((size_t)h * N_ + qr) * N_;
    const float* bias1 = bias0 + (size_t)8 * N_;

    const u32 ks0 = smem_u32(&ks_s[0][0][0]);
    const u32 vt0 = smem_u32(&vt_s[0][0][0]);
    const u32 KSB = 64 * 104 * 2;
    const u32 VTB = 64 * 72 * 2;

    const u32 lmK = (u32)(((((lane >> 4) & 1) * 8 + (lane & 7)) * 104
                           + ((lane >> 3) & 1) * 8) * 2);
    const u32 lmV = (u32)(((((lane >> 4) & 1) * 32 + (lane & 7)) * 72
                           + ((lane >> 3) & 1) * 8) * 2);

    const char* kgbase = (const char*)(g_ks + (size_t)bh * N_ * 96);
    const char* vgbase = (const char*)(g_vt + (size_t)bh * 64 * N_);

    auto stage = [&](int kt, int bf) {
        const char* src = kgbase + (size_t)kt * 64 * 192;
        u32 dst = ks0 + bf * KSB;
        #pragma unroll
        for (int i = 0; i < 3; i++) {
            int idx = i * 256 + tid;
            int key = idx / 12, seg = idx % 12;
            CP_ASYNC16(dst + (key * 104 + seg * 8) * 2, src + key * 192 + seg * 16);
        }
        const char* vs = vgbase + (size_t)kt * 64 * 2;
        u32 vdst = vt0 + bf * VTB;
        #pragma unroll
        for (int i = 0; i < 2; i++) {
            int idx = i * 256 + tid;
            int f = idx / 8, seg = idx % 8;
            CP_ASYNC16(vdst + (f * 72 + seg * 8) * 2, vs + (size_t)f * N_ * 2 + seg * 16);
        }
        CP_COMMIT();
    };

    stage(0, 0);

    for (int kt = 0; kt < 16; kt++) {
        const int buf = kt & 1;
        CP_WAIT0();
        __syncthreads();
        if (kt < 15) stage(kt + 1, buf ^ 1);

        const u32 kbase = ks0 + buf * KSB;
        const u32 vbase = vt0 + buf * VTB;

        float c[8][4];
        #pragma unroll
        for (int nt = 0; nt < 8; nt++) {
            c[nt][0] = 0.f; c[nt][1] = 0.f; c[nt][2] = 0.f; c[nt][3] = 0.f;
        }
        #pragma unroll
        for (int ks = 0; ks < 6; ks++) {
            #pragma unroll
            for (int ntp = 0; ntp < 4; ntp++) {
                u32 b00, b01, b10, b11;
                LDSM_X4(b00, b01, b10, b11,
                        kbase + lmK + (u32)((ntp * 16 * 104 + 16 * ks) * 2));
                MMA16816(c[2*ntp][0], c[2*ntp][1], c[2*ntp][2], c[2*ntp][3],
                         aQ[ks][0], aQ[ks][1], aQ[ks][2], aQ[ks][3], b00, b01);
                MMA16816(c[2*ntp+1][0], c[2*ntp+1][1], c[2*ntp+1][2], c[2*ntp+1][3],
                         aQ[ks][0], aQ[ks][1], aQ[ks][2], aQ[ks][3], b10, b11);
            }
        }

        u32 aPh[16], aPl[16];
        #pragma unroll
        for (int nt = 0; nt < 8; nt++) {
            int kg = kt * 64 + nt * 8 + fc2;
            float2 bb0 = *(const float2*)(bias0 + kg);
            float2 bb1 = *(const float2*)(bias1 + kg);
            float pv0 = __expf(fmaf(c[nt][0], scale, bb0.x - M));
            float pv1 = __expf(fmaf(c[nt][1], scale, bb0.y - M));
            float pv2 = __expf(fmaf(c[nt][2], scale, bb1.x - M));
            float pv3 = __expf(fmaf(c[nt][3], scale, bb1.y - M));
            s0 += pv0 + pv1;
            s1 += pv2 + pv3;
            __nv_bfloat16 h0 = __float2bfloat16(pv0);
            __nv_bfloat16 h1 = __float2bfloat16(pv1);
            __nv_bfloat16 h2 = __float2bfloat16(pv2);
            __nv_bfloat16 h3 = __float2bfloat16(pv3);
            aPh[nt * 2]     = pkh(h0, h1);
            aPh[nt * 2 + 1] = pkh(h2, h3);
            aPl[nt * 2]     = pkf(pv0 - __bfloat162float(h0), pv1 - __bfloat162float(h1));
            aPl[nt * 2 + 1] = pkf(pv2 - __bfloat162float(h2), pv3 - __bfloat162float(h3));
        }

        #pragma unroll
        for (int ks = 0; ks < 4; ks++) {
            #pragma unroll
            for (int nt = 0; nt < 4; nt++) {
                u32 bh0, bh1, bl0, bl1;
                LDSM_X4(bh0, bh1, bl0, bl1,
                        vbase + lmV + (u32)((nt * 8 * 72 + 16 * ks) * 2));
                MMA16816(o[nt][0], o[nt][1], o[nt][2], o[nt][3],
                         aPh[4*ks], aPh[4*ks+1], aPh[4*ks+2], aPh[4*ks+3], bh0, bh1);
                MMA16816(o[nt][0], o[nt][1], o[nt][2], o[nt][3],
                         aPl[4*ks], aPl[4*ks+1], aPl[4*ks+2], aPl[4*ks+3], bh0, bh1);
                MMA16816(o[nt][0], o[nt][1], o[nt][2], o[nt][3],
                         aPh[4*ks], aPh[4*ks+1], aPh[4*ks+2], aPh[4*ks+3], bl0, bl1);
            }
        }
    }

    s0 += __shfl_xor_sync(0xffffffffu, s0, 1);
    s0 += __shfl_xor_sync(0xffffffffu, s0, 2);
    s1 += __shfl_xor_sync(0xffffffffu, s1, 1);
    s1 += __shfl_xor_sync(0xffffffffu, s1, 2);
    float i0 = 1.f / s0, i1 = 1.f / s1;

    #pragma unroll
    for (int nt = 0; nt < 4; nt++) {
        int dd = nt * 8 + fc2;
        float2 w0 = make_float2(o[nt][0] * i0, o[nt][1] * i0);
        float2 w1 = make_float2(o[nt][2] * i1, o[nt][3] * i1);
        *(float2*)&g_o[((size_t)bh * N_ + qr) * HD_ + dd]     = w0;
        *(float2*)&g_o[((size_t)bh * N_ + qr + 8) * HD_ + dd] = w1;
    }
}

// ============================================================
// K5: output projection (padded smem, f32x2 inner). (launch index 7)
// ============================================================
__global__ void __launch_bounds__(256) proj_kernel(
    const float* __restrict__ p1w, const float* __restrict__ p1b,
    const float* __restrict__ p2w, const float* __restrict__ p2b,
    float* __restrict__ out)
{
    __shared__ float o_s[16][C_ + 1];
    __shared__ u64   w_s2[64][16];
    __shared__ float y_s[16][C_ + 1];

    const int tid  = threadIdx.x;
    const int tok0 = blockIdx.x * 16;
    const int b    = tok0 / N_;
    const int n0   = tok0 % N_;

    for (int idx = tid; idx < 16 * C_; idx += 256) {
        int t = idx >> 8, c = idx & 255;
        o_s[t][c] = g_o[(((size_t)b * NH_ + (c >> 5)) * N_ + n0 + t) * HD_ + (c & 31)];
    }
    __syncthreads();

    const float* Ws[2] = {p1w, p2w};
    const float* Bs[2] = {p1b, p2b};

    const int lane = tid & 31;
    const int warp = tid >> 5;
    const int t    = lane & 15;
    const int sub  = lane >> 4;
    const int oc0  = warp * 16 + sub * 8;
    const int p0   = oc0 >> 1;

    for (int m = 0; m < 2; m++) {
        const int half = m;
        const float* W  = Ws[m];
        const float* bb = Bs[m];
        u64 acc[4];
        #pragma unroll
        for (int u = 0; u < 4; u++)
            PACKAB(acc[u], bb[oc0 + 2*u], bb[oc0 + 2*u + 1]);

        for (int ch = 0; ch < 8; ch++) {
            __syncthreads();
            #pragma unroll
            for (int r = 0; r < 4; r++) {
                int idx = r * 256 + tid;
                int p = idx >> 4, ii = idx & 15;
                float w0 = W[(2*p)     * HALF_ + ch * 16 + ii];
                float w1 = W[(2*p + 1) * HALF_ + ch * 16 + ii];
                PACKAB(w_s2[p][ii], w0, w1);
            }
            __syncthreads();
            #pragma unroll 8
            for (int ii = 0; ii < 16; ii++) {
                u64 xx; PACK2(xx, o_s[t][half * HALF_ + ch * 16 + ii]);
                #pragma unroll
                for (int u = 0; u < 4; u++)
                    FMA2(acc[u], w_s2[p0 + u][ii], xx, acc[u]);
            }
        }
        float o[8];
        #pragma unroll
        for (int u = 0; u < 4; u++) UNPACK2(o[2*u], o[2*u+1], acc[u]);
        #pragma unroll
        for (int u = 0; u < 8; u++) y_s[t][half * HALF_ + oc0 + u] = o[u];
    }
    __syncthreads();

    for (int idx = tid; idx < 16 * C_; idx += 256) {
        int c = idx >> 4, t2 = idx & 15;
        out[((size_t)b * C_ + c) * N_ + n0 + t2] = y_s[t2][c];
    }
}

// ============================================================
extern "C" void kernel_launch(void* const* d_in, const int* in_sizes, int n_in,
                              void* d_out, int out_size)
{
    const float* x    = (const float*)d_in[0];
    const float* q1w  = (const float*)d_in[1];
    const float* q1b  = (const float*)d_in[2];
    const float* q2w  = (const float*)d_in[3];
    const float* q2b  = (const float*)d_in[4];
    const float* k1w  = (const float*)d_in[5];
    const float* k1b  = (const float*)d_in[6];
    const float* k2w  = (const float*)d_in[7];
    const float* k2b  = (const float*)d_in[8];
    const float* v1w  = (const float*)d_in[9];
    const float* v1b  = (const float*)d_in[10];
    const float* v2w  = (const float*)d_in[11];
    const float* v2b  = (const float*)d_in[12];
    const float* p1w  = (const float*)d_in[13];
    const float* p1b  = (const float*)d_in[14];
    const float* p2w  = (const float*)d_in[15];
    const float* p2b  = (const float*)d_in[16];
    const float* ls   = (const float*)d_in[17];
    const float* m1w  = (const float*)d_in[18];
    const float* m1b  = (const float*)d_in[19];
    const float* m2w  = (const float*)d_in[20];
    float* out = (float*)d_out;

    // qkvgemm sits at app-launch index 3 (the ncu slot).
    wext_kernel<<<dim3(6, 64), 256>>>(q1w, q2w, k1w, k2w, v1w, v2w);
    tab_kernel<<<(TABN_ + 255) / 256, 256>>>(m1w, m1b, m2w);
    bias_kernel<<<dim3(N_, N_ / 256), 256>>>();
    qkvgemm_kernel<<<dim3(16, 16), 256>>>(x, q1b, q2b, k1b, k2b, v1b, v2b);
    normsplit_kernel<<<dim3(8, 128, 2), 128>>>();
    vsplit_kernel<<<4096, 256>>>();
    attn_kernel<<<dim3(N_ / 128, BH_), 256>>>(ls);
    proj_kernel<<<B_ * N_ / 16, 256>>>(p1w, p1b, p2w, p2b, out);
}

// round 10
// speedup vs baseline: 3.5446x; 1.2254x over previous
#include <cuda_runtime.h>
#include <cuda_bf16.h>
#include <math.h>
#include <stdint.h>

#define B_    16
#define C_    256
#define N_    1024      // 32*32 tokens
#define NH_   8
#define HD_   32
#define HALF_ 128
#define BH_   (B_*NH_)  // 128
#define TABN_ 3969      // 63*63

typedef unsigned long long u64;
typedef unsigned int u32;

// bf16 mma m16n8k16, fp32 accum
#define MMA16816(d0,d1,d2,d3,a0,a1,a2,a3,b0,b1) \
    asm("mma.sync.aligned.m16n8k16.row.col.f32.bf16.bf16.f32 " \
        "{%0,%1,%2,%3}, {%4,%5,%6,%7}, {%8,%9}, {%0,%1,%2,%3};" \
        : "+f"(d0), "+f"(d1), "+f"(d2), "+f"(d3) \
        : "r"(a0), "r"(a1), "r"(a2), "r"(a3), "r"(b0), "r"(b1))

#define LDSM_X4(r0,r1,r2,r3,addr) \
    asm volatile("ldmatrix.sync.aligned.m8n8.x4.shared.b16 {%0,%1,%2,%3}, [%4];" \
        : "=r"(r0), "=r"(r1), "=r"(r2), "=r"(r3) : "r"(addr))

#define LDSM_X4_T(r0,r1,r2,r3,addr) \
    asm volatile("ldmatrix.sync.aligned.m8n8.x4.trans.shared.b16 {%0,%1,%2,%3}, [%4];" \
        : "=r"(r0), "=r"(r1), "=r"(r2), "=r"(r3) : "r"(addr))

#define CP_ASYNC16(dst,src) \
    asm volatile("cp.async.cg.shared.global [%0], [%1], 16;" :: "r"(dst), "l"(src))
#define CP_COMMIT() asm volatile("cp.async.commit_group;")
#define CP_WAIT0()  asm volatile("cp.async.wait_group 0;")

__device__ __forceinline__ u32 smem_u32(const void* p) {
    u32 a;
    asm("{ .reg .u64 t; cvta.to.shared.u64 t, %1; cvt.u32.u64 %0, t; }"
        : "=r"(a) : "l"(p));
    return a;
}

// ---- scratch (device globals; no runtime allocation allowed) ----
__device__ float g_q[B_*C_*N_];             // 16 MB, [b][c][tok]
__device__ float g_k[B_*C_*N_];             // 16 MB
__device__ float g_v[B_*C_*N_];             // 16 MB
__device__ u32 g_wfrag[8*8*24*32*4];        // pre-swizzled A-fragments (qkv+proj)
__device__ __nv_bfloat16 g_qs[BH_*N_*96];   // [qh|ql|qh]  25 MB
__device__ __nv_bfloat16 g_ks[BH_*N_*96];   // [kh|kh|kl]  25 MB
__device__ __nv_bfloat16 g_vt[BH_*64*N_];   // [bh][vh|vl][key] 16 MB
__device__ float g_o[BH_*N_*HD_];           // 16 MB
__device__ __nv_bfloat16 g_osh[B_*C_*N_];   // attn out, high split, [b][c][tok] 8 MB
__device__ __nv_bfloat16 g_osl[B_*C_*N_];   // low split 8 MB
__device__ float g_tab[TABN_*NH_];
__device__ float g_biasB[NH_*N_*N_];        // 32 MB, [h][query][key]

__device__ __forceinline__ u32 pkh(__nv_bfloat16 a, __nv_bfloat16 b) {
    __nv_bfloat162 t; t.x = a; t.y = b;
    return *(u32*)&t;
}
__device__ __forceinline__ u32 pkf(float a, float b) {
    __nv_bfloat162 t = __floats2bfloat162_rn(a, b);
    return *(u32*)&t;
}

// ============================================================
// K_wext: pre-swizzled split-weight A-fragments, K-ext [wh|wl|wh].
// One u32 per thread. Read side: uint4 per (m,rowblock,ks,lane).
// (launch index 0)
// ============================================================
__global__ void __launch_bounds__(256) wext_kernel(
    const float* __restrict__ q1w, const float* __restrict__ q2w,
    const float* __restrict__ k1w, const float* __restrict__ k2w,
    const float* __restrict__ v1w, const float* __restrict__ v2w,
    const float* __restrict__ p1w, const float* __restrict__ p2w)
{
    const float* Ws[8] = {q1w, q2w, k1w, k2w, v1w, v2w, p1w, p2w};
    int id = blockIdx.x * 256 + threadIdx.x;   // 0..196607
    int j    = id & 3;
    int lane = (id >> 2) & 31;
    int ks   = (id >> 7) % 24;
    int rbm  = id / (128 * 24);
    int rb = rbm & 7, m = rbm >> 3;
    int row = rb * 16 + (lane >> 2) + (j & 1) * 8;
    int col = ks * 16 + 2 * (lane & 3) + ((j >> 1) & 1) * 8;
    int region = col >> 7, ic = col & 127;
    const float* W = Ws[m];
    float v0 = W[row * 128 + ic], v1 = W[row * 128 + ic + 1];
    u32 r;
    if (region == 1) {
        __nv_bfloat16 h0 = __float2bfloat16(v0), h1 = __float2bfloat16(v1);
        r = pkf(v0 - __bfloat162float(h0), v1 - __bfloat162float(h1));
    } else {
        r = pkh(__float2bfloat16(v0), __float2bfloat16(v1));
    }
    g_wfrag[id] = r;
}

// ============================================================
// K2: CPB table MLP (launch index 1)
// ============================================================
__global__ void __launch_bounds__(256) tab_kernel(
    const float* __restrict__ w1, const float* __restrict__ b1,
    const float* __restrict__ w2)
{
    __shared__ float w1s[256];
    __shared__ float b1s[128];
    __shared__ float w2s[1024];
    int tid = threadIdx.x;
    if (tid < 256) w1s[tid] = w1[tid];
    if (tid < 128) b1s[tid] = b1[tid];
    for (int i = tid; i < 1024; i += 256) w2s[i] = w2[i];
    __syncthreads();

    int p = blockIdx.x * 256 + tid;
    if (p >= TABN_) return;
    int a = p / 63, b = p % 63;
    float t0 = ((float)(a - 31) / 31.0f) * 3.2f;
    float t1 = ((float)(b - 31) / 31.0f) * 3.2f;
    t0 = copysignf(1.f - __expf(-fabsf(t0)), t0);
    t1 = copysignf(1.f - __expf(-fabsf(t1)), t1);

    float acc[NH_];
    #pragma unroll
    for (int h = 0; h < NH_; h++) acc[h] = 0.f;
    for (int k = 0; k < 128; k++) {
        float hv = fmaxf(w1s[2 * k] * t0 + w1s[2 * k + 1] * t1 + b1s[k], 0.f);
        #pragma unroll
        for (int h = 0; h < NH_; h++) acc[h] += w2s[h * 128 + k] * hv;
    }
    #pragma unroll
    for (int h = 0; h < NH_; h++) g_tab[p * NH_ + h] = acc[h];
}

// ============================================================
// K3: expand bias to [h][query][key] (launch index 2)
// ============================================================
__global__ void __launch_bounds__(256) bias_kernel()
{
    int n = blockIdx.x;                       // query
    int m = blockIdx.y * 256 + threadIdx.x;   // key
    int i = n >> 5, j = n & 31;
    int p = m >> 5, q = m & 31;
    int idx = (i - p + 31) * 63 + (j - q + 31);
    const float* t = g_tab + idx * NH_;
    #pragma unroll
    for (int h = 0; h < NH_; h++) {
        float v = 16.f / (1.f + __expf(-t[h]));
        g_biasB[((size_t)h * N_ + n) * N_ + m] = v;
    }
}

// ============================================================
// K_qkvgemm: q/k/v projections via bf16 mma, coalesced A-fragments.
// (launch index 3 — ncu slot)
// ============================================================
__global__ void __launch_bounds__(256) qkvgemm_kernel(
    const float* __restrict__ x,
    const float* __restrict__ q1b, const float* __restrict__ q2b,
    const float* __restrict__ k1b, const float* __restrict__ k2b,
    const float* __restrict__ v1b, const float* __restrict__ v2b)
{
    __shared__ __align__(16) __nv_bfloat16 xh_s[128][72];
    __shared__ __align__(16) __nv_bfloat16 xl_s[128][72];

    const int tid  = threadIdx.x;
    const int lane = tid & 31;
    const int w    = tid >> 5;
    const int b    = blockIdx.y;
    const int tok0 = blockIdx.x * 64;
    const int r0   = w * 16 + (lane >> 2);
    const int fc2  = 2 * (lane & 3);

    const u32 xh0 = smem_u32(&xh_s[0][0]);
    const u32 xl0 = smem_u32(&xl_s[0][0]);
    const u32 lmoff = (u32)((((lane & 7) + ((lane >> 3) & 1) * 8) * 144)
                            + ((lane >> 4) & 1) * 16);

    const float* Bss[6] = {q1b, q2b, k1b, k2b, v1b, v2b};
    float* Outs[3] = {g_q, g_k, g_v};

    for (int half = 0; half < 2; half++) {
        __syncthreads();
        #pragma unroll
        for (int r = 0; r < 8; r++) {
            int idx = r * 256 + tid;
            int ch = idx >> 4, t4 = (idx & 15) * 4;
            float4 xv = *(const float4*)&x[((size_t)(b * 256 + half * 128 + ch) << 10) + tok0 + t4];
            __nv_bfloat16 h0 = __float2bfloat16(xv.x), h1 = __float2bfloat16(xv.y);
            __nv_bfloat16 h2 = __float2bfloat16(xv.z), h3 = __float2bfloat16(xv.w);
            uint2 hw = make_uint2(pkh(h0, h1), pkh(h2, h3));
            uint2 lw = make_uint2(pkf(xv.x - __bfloat162float(h0), xv.y - __bfloat162float(h1)),
                                  pkf(xv.z - __bfloat162float(h2), xv.w - __bfloat162float(h3)));
            *(uint2*)&xh_s[ch][t4] = hw;
            *(uint2*)&xl_s[ch][t4] = lw;
        }
        __syncthreads();

        for (int g = 0; g < 3; g++) {
            const int m = g * 2 + half;
            const uint4* wf = (const uint4*)g_wfrag + ((size_t)(m * 8 + w) * 24) * 32 + lane;

            float c[8][4];
            #pragma unroll
            for (int i = 0; i < 8; i++) { c[i][0] = c[i][1] = c[i][2] = c[i][3] = 0.f; }

            #pragma unroll 4
            for (int ks = 0; ks < 24; ks++) {
                uint4 aa = __ldg(&wf[ks * 32]);   // coalesced LDG.128
                u32 bb = ((ks < 16) ? xh0 : xl0) + (u32)((ks & 7) * 16 * 144) + lmoff;
                #pragma unroll
                for (int nt = 0; nt < 4; nt++) {
                    u32 f0, f1, f2, f3;
                    LDSM_X4_T(f0, f1, f2, f3, bb + nt * 32);
                    MMA16816(c[2*nt][0], c[2*nt][1], c[2*nt][2], c[2*nt][3],
                             aa.x, aa.y, aa.z, aa.w, f0, f1);
                    MMA16816(c[2*nt+1][0], c[2*nt+1][1], c[2*nt+1][2], c[2*nt+1][3],
                             aa.x, aa.y, aa.z, aa.w, f2, f3);
                }
            }

            float bb0 = __ldg(&Bss[m][r0]);
            float bb1 = __ldg(&Bss[m][r0 + 8]);
            const float* xr = x + ((size_t)(b * 256 + half * 128) << 10);
            float* op = Outs[g] + ((size_t)(b * 256 + half * 128) << 10);
            #pragma unroll
            for (int n8 = 0; n8 < 8; n8++) {
                int tok = tok0 + n8 * 8 + fc2;
                float2 rx0 = *(const float2*)&xr[((size_t)r0 << 10) + tok];
                float2 rx1 = *(const float2*)&xr[((size_t)(r0 + 8) << 10) + tok];
                float2 o0 = make_float2(c[n8][0] + rx0.x + bb0, c[n8][1] + rx0.y + bb0);
                float2 o1 = make_float2(c[n8][2] + rx1.x + bb1, c[n8][3] + rx1.y + bb1);
                *(float2*)&op[((size_t)r0 << 10) + tok] = o0;
                *(float2*)&op[((size_t)(r0 + 8) << 10) + tok] = o1;
            }
        }
    }
}

// ============================================================
// K_normsplit (launch index 4)
// ============================================================
__global__ void __launch_bounds__(128) normsplit_kernel()
{
    __shared__ float xs[32][129];
    __shared__ u32 os[128][49];

    const int tid = threadIdx.x;
    const int chunk = blockIdx.x, bh = blockIdx.y, qk = blockIdx.z;
    const int b = bh >> 3, h = bh & 7;
    const int tok0 = chunk * 128;
    const float* src = (qk ? g_k : g_q) + ((size_t)(b * 256 + h * 32) << 10) + tok0;

    #pragma unroll
    for (int r = 0; r < 8; r++) {
        int idx = r * 128 + tid;
        int ch = idx >> 5, t4 = (idx & 31) * 4;
        float4 v = *(const float4*)&src[((size_t)ch << 10) + t4];
        xs[ch][t4] = v.x; xs[ch][t4+1] = v.y; xs[ch][t4+2] = v.z; xs[ch][t4+3] = v.w;
    }
    __syncthreads();

    float vals[32]; float s = 0.f;
    #pragma unroll
    for (int ch = 0; ch < 32; ch++) { vals[ch] = xs[ch][tid]; s += vals[ch] * vals[ch]; }
    float inv = 1.f / fmaxf(sqrtf(s), 1e-12f);

    #pragma unroll
    for (int j = 0; j < 16; j++) {
        float v0 = vals[2*j] * inv, v1 = vals[2*j+1] * inv;
        __nv_bfloat16 h0 = __float2bfloat16(v0), h1 = __float2bfloat16(v1);
        u32 hh = pkh(h0, h1);
        u32 ll = pkf(v0 - __bfloat162float(h0), v1 - __bfloat162float(h1));
        if (qk == 0) { os[tid][j] = hh; os[tid][16+j] = ll; os[tid][32+j] = hh; }
        else         { os[tid][j] = hh; os[tid][16+j] = hh; os[tid][32+j] = ll; }
    }
    __syncthreads();

    __nv_bfloat16* dst = (qk ? g_ks : g_qs) + ((size_t)bh * N_ + tok0) * 96;
    #pragma unroll
    for (int r = 0; r < 12; r++) {
        int idx = r * 128 + tid;
        int row = idx / 12, seg = idx % 12;
        uint4 v = make_uint4(os[row][seg*4], os[row][seg*4+1],
                             os[row][seg*4+2], os[row][seg*4+3]);
        *(uint4*)(dst + (size_t)row * 96 + seg * 8) = v;
    }
}

// ============================================================
// K_vsplit (launch index 5)
// ============================================================
__global__ void __launch_bounds__(256) vsplit_kernel()
{
    const int row = blockIdx.x;            // b*256 + c
    const int b = row >> 8, c = row & 255;
    const int h = c >> 5, d = c & 31;
    const float* src = g_v + ((size_t)row << 10);
    __nv_bfloat16* dh = g_vt + (((size_t)(b * 8 + h)) * 64 + d) * 1024;
    __nv_bfloat16* dl = dh + 32 * 1024;
    int t4 = threadIdx.x * 4;
    float4 v = *(const float4*)&src[t4];
    __nv_bfloat16 h0 = __float2bfloat16(v.x), h1 = __float2bfloat16(v.y);
    __nv_bfloat16 h2 = __float2bfloat16(v.z), h3 = __float2bfloat16(v.w);
    uint2 hw = make_uint2(pkh(h0, h1), pkh(h2, h3));
    uint2 lw = make_uint2(pkf(v.x - __bfloat162float(h0), v.y - __bfloat162float(h1)),
                          pkf(v.z - __bfloat162float(h2), v.w - __bfloat162float(h3)));
    *(uint2*)&dh[t4] = hw;
    *(uint2*)&dl[t4] = lw;
}

// ============================================================
// K4: attention (unchanged from R8). (launch index 6)
// ============================================================
__global__ void __launch_bounds__(256, 2) attn_kernel(const float* __restrict__ logit_scale)
{
    __shared__ __align__(16) __nv_bfloat16 ks_s[2][64][104];
    __shared__ __align__(16) __nv_bfloat16 vt_s[2][64][72];

    const int tid  = threadIdx.x;
    const int lane = tid & 31;
    const int w    = tid >> 5;
    const int bh   = blockIdx.y;
    const int h    = bh & 7;
    const int q0   = blockIdx.x * 128;
    const int qr   = q0 + w * 16 + (lane >> 2);
    const int fc2  = 2 * (lane & 3);

    u32 aQ[6][4];
    {
        const __nv_bfloat16* qb = g_qs + ((size_t)bh * N_ + qr) * 96;
        #pragma unroll
        for (int ks = 0; ks < 6; ks++) {
            int f = fc2 + 16 * ks;
            aQ[ks][0] = *(const u32*)(qb + f);
            aQ[ks][1] = *(const u32*)(qb + 8 * 96 + f);
            aQ[ks][2] = *(const u32*)(qb + f + 8);
            aQ[ks][3] = *(const u32*)(qb + 8 * 96 + f + 8);
        }
    }

    const float scale = __expf(fminf(logit_scale[h], 4.6051702f)); // log(100)
    const float M = scale + 16.0f;

    float o[4][4];
    #pragma unroll
    for (int i = 0; i < 4; i++)
        #pragma unroll
        for (int j = 0; j < 4; j++) o[i][j] = 0.f;
    float s0 = 0.f, s1 = 0.f;

    const float* bias0 = g_biasB + ((size_t)h * N_ + qr) * N_;
    const float* bias1 = bias0 + (size_t)8 * N_;

    const u32 ks0 = smem_u32(&ks_s[0][0][0]);
    const u32 vt0 = smem_u32(&vt_s[0][0][0]);
    const u32 KSB = 64 * 104 * 2;
    const u32 VTB = 64 * 72 * 2;

    const u32 lmK = (u32)(((((lane >> 4) & 1) * 8 + (lane & 7)) * 104
                           + ((lane >> 3) & 1) * 8) * 2);
    const u32 lmV = (u32)(((((lane >> 4) & 1) * 32 + (lane & 7)) * 72
                           + ((lane >> 3) & 1) * 8) * 2);

    const char* kgbase = (const char*)(g_ks + (size_t)bh * N_ * 96);
    const char* vgbase = (const char*)(g_vt + (size_t)bh * 64 * N_);

    auto stage = [&](int kt, int bf) {
        const char* src = kgbase + (size_t)kt * 64 * 192;
        u32 dst = ks0 + bf * KSB;
        #pragma unroll
        for (int i = 0; i < 3; i++) {
            int idx = i * 256 + tid;
            int key = idx / 12, seg = idx % 12;
            CP_ASYNC16(dst + (key * 104 + seg * 8) * 2, src + key * 192 + seg * 16);
        }
        const char* vs = vgbase + (size_t)kt * 64 * 2;
        u32 vdst = vt0 + bf * VTB;
        #pragma unroll
        for (int i = 0; i < 2; i++) {
            int idx = i * 256 + tid;
            int f = idx / 8, seg = idx % 8;
            CP_ASYNC16(vdst + (f * 72 + seg * 8) * 2, vs + (size_t)f * N_ * 2 + seg * 16);
        }
        CP_COMMIT();
    };

    stage(0, 0);

    for (int kt = 0; kt < 16; kt++) {
        const int buf = kt & 1;
        CP_WAIT0();
        __syncthreads();
        if (kt < 15) stage(kt + 1, buf ^ 1);

        const u32 kbase = ks0 + buf * KSB;
        const u32 vbase = vt0 + buf * VTB;

        float c[8][4];
        #pragma unroll
        for (int nt = 0; nt < 8; nt++) {
            c[nt][0] = 0.f; c[nt][1] = 0.f; c[nt][2] = 0.f; c[nt][3] = 0.f;
        }
        #pragma unroll
        for (int ks = 0; ks < 6; ks++) {
            #pragma unroll
            for (int ntp = 0; ntp < 4; ntp++) {
                u32 b00, b01, b10, b11;
                LDSM_X4(b00, b01, b10, b11,
                        kbase + lmK + (u32)((ntp * 16 * 104 + 16 * ks) * 2));
                MMA16816(c[2*ntp][0], c[2*ntp][1], c[2*ntp][2], c[2*ntp][3],
                         aQ[ks][0], aQ[ks][1], aQ[ks][2], aQ[ks][3], b00, b01);
                MMA16816(c[2*ntp+1][0], c[2*ntp+1][1], c[2*ntp+1][2], c[2*ntp+1][3],
                         aQ[ks][0], aQ[ks][1], aQ[ks][2], aQ[ks][3], b10, b11);
            }
        }

        u32 aPh[16], aPl[16];
        #pragma unroll
        for (int nt = 0; nt < 8; nt++) {
            int kg = kt * 64 + nt * 8 + fc2;
            float2 bb0 = *(const float2*)(bias0 + kg);
            float2 bb1 = *(const float2*)(bias1 + kg);
            float pv0 = __expf(fmaf(c[nt][0], scale, bb0.x - M));
            float pv1 = __expf(fmaf(c[nt][1], scale, bb0.y - M));
            float pv2 = __expf(fmaf(c[nt][2], scale, bb1.x - M));
            float pv3 = __expf(fmaf(c[nt][3], scale, bb1.y - M));
            s0 += pv0 + pv1;
            s1 += pv2 + pv3;
            __nv_bfloat16 h0 = __float2bfloat16(pv0);
            __nv_bfloat16 h1 = __float2bfloat16(pv1);
            __nv_bfloat16 h2 = __float2bfloat16(pv2);
            __nv_bfloat16 h3 = __float2bfloat16(pv3);
            aPh[nt * 2]     = pkh(h0, h1);
            aPh[nt * 2 + 1] = pkh(h2, h3);
            aPl[nt * 2]     = pkf(pv0 - __bfloat162float(h0), pv1 - __bfloat162float(h1));
            aPl[nt * 2 + 1] = pkf(pv2 - __bfloat162float(h2), pv3 - __bfloat162float(h3));
        }

        #pragma unroll
        for (int ks = 0; ks < 4; ks++) {
            #pragma unroll
            for (int nt = 0; nt < 4; nt++) {
                u32 bh0, bh1, bl0, bl1;
                LDSM_X4(bh0, bh1, bl0, bl1,
                        vbase + lmV + (u32)((nt * 8 * 72 + 16 * ks) * 2));
                MMA16816(o[nt][0], o[nt][1], o[nt][2], o[nt][3],
                         aPh[4*ks], aPh[4*ks+1], aPh[4*ks+2], aPh[4*ks+3], bh0, bh1);
                MMA16816(o[nt][0], o[nt][1], o[nt][2], o[nt][3],
                         aPl[4*ks], aPl[4*ks+1], aPl[4*ks+2], aPl[4*ks+3], bh0, bh1);
                MMA16816(o[nt][0], o[nt][1], o[nt][2], o[nt][3],
                         aPh[4*ks], aPh[4*ks+1], aPh[4*ks+2], aPh[4*ks+3], bl0, bl1);
            }
        }
    }

    s0 += __shfl_xor_sync(0xffffffffu, s0, 1);
    s0 += __shfl_xor_sync(0xffffffffu, s0, 2);
    s1 += __shfl_xor_sync(0xffffffffu, s1, 1);
    s1 += __shfl_xor_sync(0xffffffffu, s1, 2);
    float i0 = 1.f / s0, i1 = 1.f / s1;

    #pragma unroll
    for (int nt = 0; nt < 4; nt++) {
        int dd = nt * 8 + fc2;
        float2 w0 = make_float2(o[nt][0] * i0, o[nt][1] * i0);
        float2 w1 = make_float2(o[nt][2] * i1, o[nt][3] * i1);
        *(float2*)&g_o[((size_t)bh * N_ + qr) * HD_ + dd]     = w0;
        *(float2*)&g_o[((size_t)bh * N_ + qr + 8) * HD_ + dd] = w1;
    }
}

// ============================================================
// K_osplit: g_o [bh][tok][d] -> channel-major bf16 splits [b][c][tok].
// (launch index 7)
// ============================================================
__global__ void __launch_bounds__(256) osplit_kernel()
{
    __shared__ float ts[32][130];
    const int tid = threadIdx.x;
    const int chunk = blockIdx.x, bh = blockIdx.y;
    const int b = bh >> 3, h = bh & 7;
    const int tok0 = chunk * 128;
    const float* src = g_o + ((size_t)(bh * 1024 + tok0)) * 32;

    #pragma unroll
    for (int r = 0; r < 4; r++) {
        int idx = r * 256 + tid;              // 0..1023 float4
        int tok = idx >> 3, d4 = (idx & 7) * 4;
        float4 v = *(const float4*)&src[tok * 32 + d4];
        ts[d4][tok] = v.x; ts[d4+1][tok] = v.y; ts[d4+2][tok] = v.z; ts[d4+3][tok] = v.w;
    }
    __syncthreads();

    const int d = tid >> 3, seg = tid & 7;    // 16 tokens per segment
    u32 hh[8], ll[8];
    #pragma unroll
    for (int i = 0; i < 8; i++) {
        float v0 = ts[d][seg * 16 + 2*i];
        float v1 = ts[d][seg * 16 + 2*i + 1];
        __nv_bfloat16 h0 = __float2bfloat16(v0), h1 = __float2bfloat16(v1);
        hh[i] = pkh(h0, h1);
        ll[i] = pkf(v0 - __bfloat162float(h0), v1 - __bfloat162float(h1));
    }
    size_t off = ((size_t)(b * 256 + h * 32 + d) << 10) + tok0 + seg * 16;
    *(uint4*)&g_osh[off]     = make_uint4(hh[0], hh[1], hh[2], hh[3]);
    *(uint4*)&g_osh[off + 8] = make_uint4(hh[4], hh[5], hh[6], hh[7]);
    *(uint4*)&g_osl[off]     = make_uint4(ll[0], ll[1], ll[2], ll[3]);
    *(uint4*)&g_osl[off + 8] = make_uint4(ll[4], ll[5], ll[6], ll[7]);
}

// ============================================================
// K_projgemm: output projection via bf16 mma; writes NCHW out.
// (launch index 8)
// ============================================================
__global__ void __launch_bounds__(256) projgemm_kernel(
    const float* __restrict__ p1b, const float* __restrict__ p2b,
    float* __restrict__ out)
{
    __shared__ __align__(16) __nv_bfloat16 xh_s[128][72];
    __shared__ __align__(16) __nv_bfloat16 xl_s[128][72];

    const int tid  = threadIdx.x;
    const int lane = tid & 31;
    const int w    = tid >> 5;
    const int b    = blockIdx.y;
    const int tok0 = blockIdx.x * 64;
    const int r0   = w * 16 + (lane >> 2);
    const int fc2  = 2 * (lane & 3);

    const u32 xh0 = smem_u32(&xh_s[0][0]);
    const u32 xl0 = smem_u32(&xl_s[0][0]);
    const u32 lmoff = (u32)((((lane & 7) + ((lane >> 3) & 1) * 8) * 144)
                            + ((lane >> 4) & 1) * 16);

    const float* Bss[2] = {p1b, p2b};

    for (int half = 0; half < 2; half++) {
        __syncthreads();
        {
            const char* sh = (const char*)g_osh
                + (((size_t)(b * 256 + half * 128) << 10) + tok0) * 2;
            const char* sl = (const char*)g_osl
                + (((size_t)(b * 256 + half * 128) << 10) + tok0) * 2;
            #pragma unroll
            for (int r = 0; r < 4; r++) {
                int idx = r * 256 + tid;          // 0..1023
                int ch = idx >> 3, seg = idx & 7;
                CP_ASYNC16(xh0 + (ch * 72 + seg * 8) * 2, sh + ((size_t)ch << 11) + seg * 16);
                CP_ASYNC16(xl0 + (ch * 72 + seg * 8) * 2, sl + ((size_t)ch << 11) + seg * 16);
            }
            CP_COMMIT(); CP_WAIT0();
        }
        __syncthreads();

        const int m = 6 + half;
        const uint4* wf = (const uint4*)g_wfrag + ((size_t)(m * 8 + w) * 24) * 32 + lane;

        float c[8][4];
        #pragma unroll
        for (int i = 0; i < 8; i++) { c[i][0] = c[i][1] = c[i][2] = c[i][3] = 0.f; }

        #pragma unroll 4
        for (int ks = 0; ks < 24; ks++) {
            uint4 aa = __ldg(&wf[ks * 32]);
            u32 bb = ((ks < 16) ? xh0 : xl0) + (u32)((ks & 7) * 16 * 144) + lmoff;
            #pragma unroll
            for (int nt = 0; nt < 4; nt++) {
                u32 f0, f1, f2, f3;
                LDSM_X4_T(f0, f1, f2, f3, bb + nt * 32);
                MMA16816(c[2*nt][0], c[2*nt][1], c[2*nt][2], c[2*nt][3],
                         aa.x, aa.y, aa.z, aa.w, f0, f1);
                MMA16816(c[2*nt+1][0], c[2*nt+1][1], c[2*nt+1][2], c[2*nt+1][3],
                         aa.x, aa.y, aa.z, aa.w, f2, f3);
            }
        }

        float bb0 = __ldg(&Bss[half][r0]);
        float bb1 = __ldg(&Bss[half][r0 + 8]);
        float* op = out + ((size_t)(b * 256 + half * 128) << 10);
        #pragma unroll
        for (int n8 = 0; n8 < 8; n8++) {
            int tok = tok0 + n8 * 8 + fc2;
            float2 o0 = make_float2(c[n8][0] + bb0, c[n8][1] + bb0);
            float2 o1 = make_float2(c[n8][2] + bb1, c[n8][3] + bb1);
            *(float2*)&op[((size_t)r0 << 10) + tok] = o0;
            *(float2*)&op[((size_t)(r0 + 8) << 10) + tok] = o1;
        }
    }
}

// ============================================================
extern "C" void kernel_launch(void* const* d_in, const int* in_sizes, int n_in,
                              void* d_out, int out_size)
{
    const float* x    = (const float*)d_in[0];
    const float* q1w  = (const float*)d_in[1];
    const float* q1b  = (const float*)d_in[2];
    const float* q2w  = (const float*)d_in[3];
    const float* q2b  = (const float*)d_in[4];
    const float* k1w  = (const float*)d_in[5];
    const float* k1b  = (const float*)d_in[6];
    const float* k2w  = (const float*)d_in[7];
    const float* k2b  = (const float*)d_in[8];
    const float* v1w  = (const float*)d_in[9];
    const float* v1b  = (const float*)d_in[10];
    const float* v2w  = (const float*)d_in[11];
    const float* v2b  = (const float*)d_in[12];
    const float* p1w  = (const float*)d_in[13];
    const float* p1b  = (const float*)d_in[14];
    const float* p2w  = (const float*)d_in[15];
    const float* p2b  = (const float*)d_in[16];
    const float* ls   = (const float*)d_in[17];
    const float* m1w  = (const float*)d_in[18];
    const float* m1b  = (const float*)d_in[19];
    const float* m2w  = (const float*)d_in[20];
    float* out = (float*)d_out;

    // qkvgemm sits at app-launch index 3 (the ncu slot).
    wext_kernel<<<768, 256>>>(q1w, q2w, k1w, k2w, v1w, v2w, p1w, p2w);
    tab_kernel<<<(TABN_ + 255) / 256, 256>>>(m1w, m1b, m2w);
    bias_kernel<<<dim3(N_, N_ / 256), 256>>>();
    qkvgemm_kernel<<<dim3(16, 16), 256>>>(x, q1b, q2b, k1b, k2b, v1b, v2b);
    normsplit_kernel<<<dim3(8, 128, 2), 128>>>();
    vsplit_kernel<<<4096, 256>>>();
    attn_kernel<<<dim3(N_ / 128, BH_), 256>>>(ls);
    osplit_kernel<<<dim3(8, 128), 256>>>();
    projgemm_kernel<<<dim3(16, 16), 256>>>(p1b, p2b, out);
}

// round 11
// speedup vs baseline: 3.8057x; 1.0737x over previous
#include <cuda_runtime.h>
#include <cuda_bf16.h>
#include <math.h>
#include <stdint.h>

#define B_    16
#define C_    256
#define N_    1024      // 32*32 tokens
#define NH_   8
#define HD_   32
#define HALF_ 128
#define BH_   (B_*NH_)  // 128
#define TABN_ 3969      // 63*63

typedef unsigned long long u64;
typedef unsigned int u32;

// bf16 mma m16n8k16, fp32 accum
#define MMA16816(d0,d1,d2,d3,a0,a1,a2,a3,b0,b1) \
    asm("mma.sync.aligned.m16n8k16.row.col.f32.bf16.bf16.f32 " \
        "{%0,%1,%2,%3}, {%4,%5,%6,%7}, {%8,%9}, {%0,%1,%2,%3};" \
        : "+f"(d0), "+f"(d1), "+f"(d2), "+f"(d3) \
        : "r"(a0), "r"(a1), "r"(a2), "r"(a3), "r"(b0), "r"(b1))

#define LDSM_X4(r0,r1,r2,r3,addr) \
    asm volatile("ldmatrix.sync.aligned.m8n8.x4.shared.b16 {%0,%1,%2,%3}, [%4];" \
        : "=r"(r0), "=r"(r1), "=r"(r2), "=r"(r3) : "r"(addr))

#define LDSM_X4_T(r0,r1,r2,r3,addr) \
    asm volatile("ldmatrix.sync.aligned.m8n8.x4.trans.shared.b16 {%0,%1,%2,%3}, [%4];" \
        : "=r"(r0), "=r"(r1), "=r"(r2), "=r"(r3) : "r"(addr))

#define CP_ASYNC16(dst,src) \
    asm volatile("cp.async.cg.shared.global [%0], [%1], 16;" :: "r"(dst), "l"(src))
#define CP_COMMIT() asm volatile("cp.async.commit_group;")
#define CP_WAIT0()  asm volatile("cp.async.wait_group 0;")

__device__ __forceinline__ u32 smem_u32(const void* p) {
    u32 a;
    asm("{ .reg .u64 t; cvta.to.shared.u64 t, %1; cvt.u32.u64 %0, t; }"
        : "=r"(a) : "l"(p));
    return a;
}

// ---- scratch (device globals; no runtime allocation allowed) ----
__device__ float g_q[B_*C_*N_];             // 16 MB, [b][c][tok]
__device__ float g_k[B_*C_*N_];             // 16 MB
__device__ u32 g_wfrag[8*8*24*32*4];        // pre-swizzled A-fragments (qkv+proj)
__device__ __nv_bfloat16 g_qs[BH_*N_*96];   // [qh|ql|qh]  25 MB
__device__ __nv_bfloat16 g_ks[BH_*N_*96];   // [kh|kh|kl]  25 MB
__device__ __nv_bfloat16 g_vt[BH_*64*N_];   // [bh][vh|vl][key] 16 MB
__device__ float g_o[BH_*N_*HD_];           // 16 MB
__device__ __nv_bfloat16 g_osh[B_*C_*N_];   // attn out, high split, [b][c][tok]
__device__ __nv_bfloat16 g_osl[B_*C_*N_];   // low split
__device__ float g_tab[TABN_*NH_];
__device__ float g_biasB[NH_*N_*N_];        // 32 MB, [h][query][key], pre-scaled

__device__ __forceinline__ u32 pkh(__nv_bfloat16 a, __nv_bfloat16 b) {
    __nv_bfloat162 t; t.x = a; t.y = b;
    return *(u32*)&t;
}
__device__ __forceinline__ u32 pkf(float a, float b) {
    __nv_bfloat162 t = __floats2bfloat162_rn(a, b);
    return *(u32*)&t;
}
// split (v0,v1) into packed bf16x2 high + low words (low lane = v0)
__device__ __forceinline__ void split2(float v0, float v1, u32& hw, u32& lw) {
    asm("cvt.rn.bf16x2.f32 %0, %1, %2;" : "=r"(hw) : "f"(v1), "f"(v0));
    float h0 = __uint_as_float(hw << 16);
    float h1 = __uint_as_float(hw & 0xffff0000u);
    float l0 = v0 - h0, l1 = v1 - h1;
    asm("cvt.rn.bf16x2.f32 %0, %1, %2;" : "=r"(lw) : "f"(l1), "f"(l0));
}

// ============================================================
// K_wext: pre-swizzled split-weight A-fragments, K-ext [wh|wl|wh].
// (launch index 0)
// ============================================================
__global__ void __launch_bounds__(256) wext_kernel(
    const float* __restrict__ q1w, const float* __restrict__ q2w,
    const float* __restrict__ k1w, const float* __restrict__ k2w,
    const float* __restrict__ v1w, const float* __restrict__ v2w,
    const float* __restrict__ p1w, const float* __restrict__ p2w)
{
    const float* Ws[8] = {q1w, q2w, k1w, k2w, v1w, v2w, p1w, p2w};
    int id = blockIdx.x * 256 + threadIdx.x;   // 0..196607
    int j    = id & 3;
    int lane = (id >> 2) & 31;
    int ks   = (id >> 7) % 24;
    int rbm  = id / (128 * 24);
    int rb = rbm & 7, m = rbm >> 3;
    int row = rb * 16 + (lane >> 2) + (j & 1) * 8;
    int col = ks * 16 + 2 * (lane & 3) + ((j >> 1) & 1) * 8;
    int region = col >> 7, ic = col & 127;
    const float* W = Ws[m];
    float v0 = W[row * 128 + ic], v1 = W[row * 128 + ic + 1];
    u32 r;
    if (region == 1) {
        __nv_bfloat16 h0 = __float2bfloat16(v0), h1 = __float2bfloat16(v1);
        r = pkf(v0 - __bfloat162float(h0), v1 - __bfloat162float(h1));
    } else {
        r = pkh(__float2bfloat16(v0), __float2bfloat16(v1));
    }
    g_wfrag[id] = r;
}

// ============================================================
// K2: CPB table MLP (launch index 1)
// ============================================================
__global__ void __launch_bounds__(256) tab_kernel(
    const float* __restrict__ w1, const float* __restrict__ b1,
    const float* __restrict__ w2)
{
    __shared__ float w1s[256];
    __shared__ float b1s[128];
    __shared__ float w2s[1024];
    int tid = threadIdx.x;
    if (tid < 256) w1s[tid] = w1[tid];
    if (tid < 128) b1s[tid] = b1[tid];
    for (int i = tid; i < 1024; i += 256) w2s[i] = w2[i];
    __syncthreads();

    int p = blockIdx.x * 256 + tid;
    if (p >= TABN_) return;
    int a = p / 63, b = p % 63;
    float t0 = ((float)(a - 31) / 31.0f) * 3.2f;
    float t1 = ((float)(b - 31) / 31.0f) * 3.2f;
    t0 = copysignf(1.f - __expf(-fabsf(t0)), t0);
    t1 = copysignf(1.f - __expf(-fabsf(t1)), t1);

    float acc[NH_];
    #pragma unroll
    for (int h = 0; h < NH_; h++) acc[h] = 0.f;
    for (int k = 0; k < 128; k++) {
        float hv = fmaxf(w1s[2 * k] * t0 + w1s[2 * k + 1] * t1 + b1s[k], 0.f);
        #pragma unroll
        for (int h = 0; h < NH_; h++) acc[h] += w2s[h * 128 + k] * hv;
    }
    #pragma unroll
    for (int h = 0; h < NH_; h++) g_tab[p * NH_ + h] = acc[h];
}

// ============================================================
// K3: expand bias to [h][query][key], stored pre-scaled as
// (bias - M_h) * log2(e) so attn uses a single exp2(fma()).
// (launch index 2)
// ============================================================
__global__ void __launch_bounds__(256) bias_kernel(const float* __restrict__ ls)
{
    __shared__ float mh[NH_];
    if (threadIdx.x < NH_)
        mh[threadIdx.x] = __expf(fminf(ls[threadIdx.x], 4.6051702f)) + 16.f;
    __syncthreads();

    int n = blockIdx.x;                       // query
    int m = blockIdx.y * 256 + threadIdx.x;   // key
    int i = n >> 5, j = n & 31;
    int p = m >> 5, q = m & 31;
    int idx = (i - p + 31) * 63 + (j - q + 31);
    const float* t = g_tab + idx * NH_;
    #pragma unroll
    for (int h = 0; h < NH_; h++) {
        float v = 16.f / (1.f + __expf(-t[h]));
        g_biasB[((size_t)h * N_ + n) * N_ + m] = (v - mh[h]) * 1.44269504f;
    }
}

// ============================================================
// K_qkvgemm: q/k/v projections via bf16 mma, coalesced A-fragments,
// depth-1 A prefetch; v-epilogue writes g_vt splits directly.
// (launch index 3 — ncu slot)
// ============================================================
__global__ void __launch_bounds__(256) qkvgemm_kernel(
    const float* __restrict__ x,
    const float* __restrict__ q1b, const float* __restrict__ q2b,
    const float* __restrict__ k1b, const float* __restrict__ k2b,
    const float* __restrict__ v1b, const float* __restrict__ v2b)
{
    __shared__ __align__(16) __nv_bfloat16 xh_s[128][72];
    __shared__ __align__(16) __nv_bfloat16 xl_s[128][72];

    const int tid  = threadIdx.x;
    const int lane = tid & 31;
    const int w    = tid >> 5;
    const int b    = blockIdx.y;
    const int tok0 = blockIdx.x * 64;
    const int r0   = w * 16 + (lane >> 2);
    const int fc2  = 2 * (lane & 3);

    const u32 xh0 = smem_u32(&xh_s[0][0]);
    const u32 xl0 = smem_u32(&xl_s[0][0]);
    const u32 lmoff = (u32)((((lane & 7) + ((lane >> 3) & 1) * 8) * 144)
                            + ((lane >> 4) & 1) * 16);

    const float* Bss[6] = {q1b, q2b, k1b, k2b, v1b, v2b};

    for (int half = 0; half < 2; half++) {
        __syncthreads();
        #pragma unroll
        for (int r = 0; r < 8; r++) {
            int idx = r * 256 + tid;
            int ch = idx >> 4, t4 = (idx & 15) * 4;
            float4 xv = *(const float4*)&x[((size_t)(b * 256 + half * 128 + ch) << 10) + tok0 + t4];
            u32 hw0, lw0, hw1, lw1;
            split2(xv.x, xv.y, hw0, lw0);
            split2(xv.z, xv.w, hw1, lw1);
            *(uint2*)&xh_s[ch][t4] = make_uint2(hw0, hw1);
            *(uint2*)&xl_s[ch][t4] = make_uint2(lw0, lw1);
        }
        __syncthreads();

        for (int g = 0; g < 3; g++) {
            const int m = g * 2 + half;
            const uint4* wf = (const uint4*)g_wfrag + ((size_t)(m * 8 + w) * 24) * 32 + lane;

            float c[8][4];
            #pragma unroll
            for (int i = 0; i < 8; i++) { c[i][0] = c[i][1] = c[i][2] = c[i][3] = 0.f; }

            uint4 aa = __ldg(&wf[0]);
            #pragma unroll 4
            for (int ks = 0; ks < 24; ks++) {
                uint4 nxt = aa;
                if (ks < 23) nxt = __ldg(&wf[(ks + 1) * 32]);
                u32 bb = ((ks < 16) ? xh0 : xl0) + (u32)((ks & 7) * 16 * 144) + lmoff;
                #pragma unroll
                for (int nt = 0; nt < 4; nt++) {
                    u32 f0, f1, f2, f3;
                    LDSM_X4_T(f0, f1, f2, f3, bb + nt * 32);
                    MMA16816(c[2*nt][0], c[2*nt][1], c[2*nt][2], c[2*nt][3],
                             aa.x, aa.y, aa.z, aa.w, f0, f1);
                    MMA16816(c[2*nt+1][0], c[2*nt+1][1], c[2*nt+1][2], c[2*nt+1][3],
                             aa.x, aa.y, aa.z, aa.w, f2, f3);
                }
                aa = nxt;
            }

            float bb0 = __ldg(&Bss[m][r0]);
            float bb1 = __ldg(&Bss[m][r0 + 8]);
            const float* xr = x + ((size_t)(b * 256 + half * 128) << 10);

            if (g < 2) {
                float* op = (g == 0 ? g_q : g_k) + ((size_t)(b * 256 + half * 128) << 10);
                #pragma unroll
                for (int n8 = 0; n8 < 8; n8++) {
                    int tok = tok0 + n8 * 8 + fc2;
                    float2 rx0 = *(const float2*)&xr[((size_t)r0 << 10) + tok];
                    float2 rx1 = *(const float2*)&xr[((size_t)(r0 + 8) << 10) + tok];
                    float2 o0 = make_float2(c[n8][0] + rx0.x + bb0, c[n8][1] + rx0.y + bb0);
                    float2 o1 = make_float2(c[n8][2] + rx1.x + bb1, c[n8][3] + rx1.y + bb1);
                    *(float2*)&op[((size_t)r0 << 10) + tok] = o0;
                    *(float2*)&op[((size_t)(r0 + 8) << 10) + tok] = o1;
                }
            } else {
                // v: write split-bf16 directly to g_vt [bh][vh|vl][tok]
                int c0 = half * 128 + r0;
                int hh_ = c0 >> 5, d0_ = c0 & 31, d1_ = (c0 + 8) & 31;
                __nv_bfloat16* vh0 = g_vt + (((size_t)(b * 8 + hh_)) * 64 + d0_) * 1024;
                __nv_bfloat16* vl0 = vh0 + (size_t)32 * 1024 - (size_t)d0_ * 1024 + (size_t)(32 + d0_) * 1024 - (size_t)32 * 1024; // = vh0 + 32*1024
                vl0 = vh0 + 32 * 1024;
                __nv_bfloat16* vh1 = g_vt + (((size_t)(b * 8 + hh_)) * 64 + d1_) * 1024;
                __nv_bfloat16* vl1 = vh1 + 32 * 1024;
                #pragma unroll
                for (int n8 = 0; n8 < 8; n8++) {
                    int tok = tok0 + n8 * 8 + fc2;
                    float2 rx0 = *(const float2*)&xr[((size_t)r0 << 10) + tok];
                    float2 rx1 = *(const float2*)&xr[((size_t)(r0 + 8) << 10) + tok];
                    float v00 = c[n8][0] + rx0.x + bb0, v01 = c[n8][1] + rx0.y + bb0;
                    float v10 = c[n8][2] + rx1.x + bb1, v11 = c[n8][3] + rx1.y + bb1;
                    u32 hw, lw;
                    split2(v00, v01, hw, lw);
                    *(u32*)&vh0[tok] = hw; *(u32*)&vl0[tok] = lw;
                    split2(v10, v11, hw, lw);
                    *(u32*)&vh1[tok] = hw; *(u32*)&vl1[tok] = lw;
                }
            }
        }
    }
}

// ============================================================
// K_normsplit (launch index 4)
// ============================================================
__global__ void __launch_bounds__(128) normsplit_kernel()
{
    __shared__ float xs[32][129];
    __shared__ u32 os[128][49];

    const int tid = threadIdx.x;
    const int chunk = blockIdx.x, bh = blockIdx.y, qk = blockIdx.z;
    const int b = bh >> 3, h = bh & 7;
    const int tok0 = chunk * 128;
    const float* src = (qk ? g_k : g_q) + ((size_t)(b * 256 + h * 32) << 10) + tok0;

    #pragma unroll
    for (int r = 0; r < 8; r++) {
        int idx = r * 128 + tid;
        int ch = idx >> 5, t4 = (idx & 31) * 4;
        float4 v = *(const float4*)&src[((size_t)ch << 10) + t4];
        xs[ch][t4] = v.x; xs[ch][t4+1] = v.y; xs[ch][t4+2] = v.z; xs[ch][t4+3] = v.w;
    }
    __syncthreads();

    float vals[32]; float s = 0.f;
    #pragma unroll
    for (int ch = 0; ch < 32; ch++) { vals[ch] = xs[ch][tid]; s += vals[ch] * vals[ch]; }
    float inv = 1.f / fmaxf(sqrtf(s), 1e-12f);

    #pragma unroll
    for (int j = 0; j < 16; j++) {
        float v0 = vals[2*j] * inv, v1 = vals[2*j+1] * inv;
        u32 hh, ll;
        split2(v0, v1, hh, ll);
        if (qk == 0) { os[tid][j] = hh; os[tid][16+j] = ll; os[tid][32+j] = hh; }
        else         { os[tid][j] = hh; os[tid][16+j] = hh; os[tid][32+j] = ll; }
    }
    __syncthreads();

    __nv_bfloat16* dst = (qk ? g_ks : g_qs) + ((size_t)bh * N_ + tok0) * 96;
    #pragma unroll
    for (int r = 0; r < 12; r++) {
        int idx = r * 128 + tid;
        int row = idx / 12, seg = idx % 12;
        uint4 v = make_uint4(os[row][seg*4], os[row][seg*4+1],
                             os[row][seg*4+2], os[row][seg*4+3]);
        *(uint4*)(dst + (size_t)row * 96 + seg * 8) = v;
    }
}

// ============================================================
// K4: attention — chunked tile (QK->softmax->PV per 16 keys) for
// cross-phase ILP; exp2 with pre-scaled bias. (launch index 5)
// ============================================================
__global__ void __launch_bounds__(256, 2) attn_kernel(const float* __restrict__ logit_scale)
{
    __shared__ __align__(16) __nv_bfloat16 ks_s[2][64][104];
    __shared__ __align__(16) __nv_bfloat16 vt_s[2][64][72];

    const int tid  = threadIdx.x;
    const int lane = tid & 31;
    const int w    = tid >> 5;
    const int bh   = blockIdx.y;
    const int h    = bh & 7;
    const int q0   = blockIdx.x * 128;
    const int qr   = q0 + w * 16 + (lane >> 2);
    const int fc2  = 2 * (lane & 3);

    u32 aQ[6][4];
    {
        const __nv_bfloat16* qb = g_qs + ((size_t)bh * N_ + qr) * 96;
        #pragma unroll
        for (int ks = 0; ks < 6; ks++) {
            int f = fc2 + 16 * ks;
            aQ[ks][0] = *(const u32*)(qb + f);
            aQ[ks][1] = *(const u32*)(qb + 8 * 96 + f);
            aQ[ks][2] = *(const u32*)(qb + f + 8);
            aQ[ks][3] = *(const u32*)(qb + 8 * 96 + f + 8);
        }
    }

    const float scale = __expf(fminf(logit_scale[h], 4.6051702f));
    const float sl2e  = scale * 1.44269504f;

    float o[4][4];
    #pragma unroll
    for (int i = 0; i < 4; i++)
        #pragma unroll
        for (int j = 0; j < 4; j++) o[i][j] = 0.f;
    float s0 = 0.f, s1 = 0.f;

    const float* bias0 = g_biasB + ((size_t)h * N_ + qr) * N_;
    const float* bias1 = bias0 + (size_t)8 * N_;

    const u32 ks0 = smem_u32(&ks_s[0][0][0]);
    const u32 vt0 = smem_u32(&vt_s[0][0][0]);
    const u32 KSB = 64 * 104 * 2;
    const u32 VTB = 64 * 72 * 2;

    const u32 lmK = (u32)(((((lane >> 4) & 1) * 8 + (lane & 7)) * 104
                           + ((lane >> 3) & 1) * 8) * 2);
    const u32 lmV = (u32)(((((lane >> 4) & 1) * 32 + (lane & 7)) * 72
                           + ((lane >> 3) & 1) * 8) * 2);

    const char* kgbase = (const char*)(g_ks + (size_t)bh * N_ * 96);
    const char* vgbase = (const char*)(g_vt + (size_t)bh * 64 * N_);

    auto stage = [&](int kt, int bf) {
        const char* src = kgbase + (size_t)kt * 64 * 192;
        u32 dst = ks0 + bf * KSB;
        #pragma unroll
        for (int i = 0; i < 3; i++) {
            int idx = i * 256 + tid;
            int key = idx / 12, seg = idx % 12;
            CP_ASYNC16(dst + (key * 104 + seg * 8) * 2, src + key * 192 + seg * 16);
        }
        const char* vs = vgbase + (size_t)kt * 64 * 2;
        u32 vdst = vt0 + bf * VTB;
        #pragma unroll
        for (int i = 0; i < 2; i++) {
            int idx = i * 256 + tid;
            int f = idx / 8, seg = idx % 8;
            CP_ASYNC16(vdst + (f * 72 + seg * 8) * 2, vs + (size_t)f * N_ * 2 + seg * 16);
        }
        CP_COMMIT();
    };

    stage(0, 0);

    for (int kt = 0; kt < 16; kt++) {
        const int buf = kt & 1;
        CP_WAIT0();
        __syncthreads();
        if (kt < 15) stage(kt + 1, buf ^ 1);

        const u32 kbase = ks0 + buf * KSB;
        const u32 vbase = vt0 + buf * VTB;

        #pragma unroll
        for (int kc = 0; kc < 4; kc++) {
            // ---- QK^T for 16 keys ----
            float c[2][4];
            c[0][0] = c[0][1] = c[0][2] = c[0][3] = 0.f;
            c[1][0] = c[1][1] = c[1][2] = c[1][3] = 0.f;
            #pragma unroll
            for (int ks = 0; ks < 6; ks++) {
                u32 b00, b01, b10, b11;
                LDSM_X4(b00, b01, b10, b11,
                        kbase + lmK + (u32)((kc * 16 * 104 + 16 * ks) * 2));
                MMA16816(c[0][0], c[0][1], c[0][2], c[0][3],
                         aQ[ks][0], aQ[ks][1], aQ[ks][2], aQ[ks][3], b00, b01);
                MMA16816(c[1][0], c[1][1], c[1][2], c[1][3],
                         aQ[ks][0], aQ[ks][1], aQ[ks][2], aQ[ks][3], b10, b11);
            }

            // ---- softmax slice (bias pre-scaled by log2e, M folded) ----
            int kg = kt * 64 + kc * 16 + fc2;
            float2 bb0 = *(const float2*)(bias0 + kg);
            float2 bb1 = *(const float2*)(bias1 + kg);
            float2 bb2 = *(const float2*)(bias0 + kg + 8);
            float2 bb3 = *(const float2*)(bias1 + kg + 8);
            float pv0 = exp2f(fmaf(c[0][0], sl2e, bb0.x));
            float pv1 = exp2f(fmaf(c[0][1], sl2e, bb0.y));
            float pv2 = exp2f(fmaf(c[0][2], sl2e, bb1.x));
            float pv3 = exp2f(fmaf(c[0][3], sl2e, bb1.y));
            float pw0 = exp2f(fmaf(c[1][0], sl2e, bb2.x));
            float pw1 = exp2f(fmaf(c[1][1], sl2e, bb2.y));
            float pw2 = exp2f(fmaf(c[1][2], sl2e, bb3.x));
            float pw3 = exp2f(fmaf(c[1][3], sl2e, bb3.y));
            s0 += (pv0 + pv1) + (pw0 + pw1);
            s1 += (pv2 + pv3) + (pw2 + pw3);

            u32 aPh[4], aPl[4];
            split2(pv0, pv1, aPh[0], aPl[0]);
            split2(pv2, pv3, aPh[1], aPl[1]);
            split2(pw0, pw1, aPh[2], aPl[2]);
            split2(pw2, pw3, aPh[3], aPl[3]);

            // ---- P·V for these 16 keys ----
            #pragma unroll
            for (int nt = 0; nt < 4; nt++) {
                u32 bh0, bh1, bl0, bl1;
                LDSM_X4(bh0, bh1, bl0, bl1,
                        vbase + lmV + (u32)((nt * 8 * 72 + 16 * kc) * 2));
                MMA16816(o[nt][0], o[nt][1], o[nt][2], o[nt][3],
                         aPh[0], aPh[1], aPh[2], aPh[3], bh0, bh1);
                MMA16816(o[nt][0], o[nt][1], o[nt][2], o[nt][3],
                         aPl[0], aPl[1], aPl[2], aPl[3], bh0, bh1);
                MMA16816(o[nt][0], o[nt][1], o[nt][2], o[nt][3],
                         aPh[0], aPh[1], aPh[2], aPh[3], bl0, bl1);
            }
        }
    }

    s0 += __shfl_xor_sync(0xffffffffu, s0, 1);
    s0 += __shfl_xor_sync(0xffffffffu, s0, 2);
    s1 += __shfl_xor_sync(0xffffffffu, s1, 1);
    s1 += __shfl_xor_sync(0xffffffffu, s1, 2);
    float i0 = 1.f / s0, i1 = 1.f / s1;

    #pragma unroll
    for (int nt = 0; nt < 4; nt++) {
        int dd = nt * 8 + fc2;
        float2 w0 = make_float2(o[nt][0] * i0, o[nt][1] * i0);
        float2 w1 = make_float2(o[nt][2] * i1, o[nt][3] * i1);
        *(float2*)&g_o[((size_t)bh * N_ + qr) * HD_ + dd]     = w0;
        *(float2*)&g_o[((size_t)bh * N_ + qr + 8) * HD_ + dd] = w1;
    }
}

// ============================================================
// K_osplit: g_o [bh][tok][d] -> channel-major bf16 splits.
// (launch index 6)
// ============================================================
__global__ void __launch_bounds__(256) osplit_kernel()
{
    __shared__ float ts[32][130];
    const int tid = threadIdx.x;
    const int chunk = blockIdx.x, bh = blockIdx.y;
    const int b = bh >> 3, h = bh & 7;
    const int tok0 = chunk * 128;
    const float* src = g_o + ((size_t)(bh * 1024 + tok0)) * 32;

    #pragma unroll
    for (int r = 0; r < 4; r++) {
        int idx = r * 256 + tid;
        int tok = idx >> 3, d4 = (idx & 7) * 4;
        float4 v = *(const float4*)&src[tok * 32 + d4];
        ts[d4][tok] = v.x; ts[d4+1][tok] = v.y; ts[d4+2][tok] = v.z; ts[d4+3][tok] = v.w;
    }
    __syncthreads();

    const int d = tid >> 3, seg = tid & 7;
    u32 hh[8], ll[8];
    #pragma unroll
    for (int i = 0; i < 8; i++) {
        float v0 = ts[d][seg * 16 + 2*i];
        float v1 = ts[d][seg * 16 + 2*i + 1];
        split2(v0, v1, hh[i], ll[i]);
    }
    size_t off = ((size_t)(b * 256 + h * 32 + d) << 10) + tok0 + seg * 16;
    *(uint4*)&g_osh[off]     = make_uint4(hh[0], hh[1], hh[2], hh[3]);
    *(uint4*)&g_osh[off + 8] = make_uint4(hh[4], hh[5], hh[6], hh[7]);
    *(uint4*)&g_osl[off]     = make_uint4(ll[0], ll[1], ll[2], ll[3]);
    *(uint4*)&g_osl[off + 8] = make_uint4(ll[4], ll[5], ll[6], ll[7]);
}

// ============================================================
// K_projgemm: output projection via bf16 mma; writes NCHW out.
// (launch index 7)
// ============================================================
__global__ void __launch_bounds__(256) projgemm_kernel(
    const float* __restrict__ p1b, const float* __restrict__ p2b,
    float* __restrict__ out)
{
    __shared__ __align__(16) __nv_bfloat16 xh_s[128][72];
    __shared__ __align__(16) __nv_bfloat16 xl_s[128][72];

    const int tid  = threadIdx.x;
    const int lane = tid & 31;
    const int w    = tid >> 5;
    const int b    = blockIdx.y;
    const int tok0 = blockIdx.x * 64;
    const int r0   = w * 16 + (lane >> 2);
    const int fc2  = 2 * (lane & 3);

    const u32 xh0 = smem_u32(&xh_s[0][0]);
    const u32 xl0 = smem_u32(&xl_s[0][0]);
    const u32 lmoff = (u32)((((lane & 7) + ((lane >> 3) & 1) * 8) * 144)
                            + ((lane >> 4) & 1) * 16);

    const float* Bss[2] = {p1b, p2b};

    for (int half = 0; half < 2; half++) {
        __syncthreads();
        {
            const char* sh = (const char*)g_osh
                + (((size_t)(b * 256 + half * 128) << 10) + tok0) * 2;
            const char* sl = (const char*)g_osl
                + (((size_t)(b * 256 + half * 128) << 10) + tok0) * 2;
            #pragma unroll
            for (int r = 0; r < 4; r++) {
                int idx = r * 256 + tid;
                int ch = idx >> 3, seg = idx & 7;
                CP_ASYNC16(xh0 + (ch * 72 + seg * 8) * 2, sh + ((size_t)ch << 11) + seg * 16);
                CP_ASYNC16(xl0 + (ch * 72 + seg * 8) * 2, sl + ((size_t)ch << 11) + seg * 16);
            }
            CP_COMMIT(); CP_WAIT0();
        }
        __syncthreads();

        const int m = 6 + half;
        const uint4* wf = (const uint4*)g_wfrag + ((size_t)(m * 8 + w) * 24) * 32 + lane;

        float c[8][4];
        #pragma unroll
        for (int i = 0; i < 8; i++) { c[i][0] = c[i][1] = c[i][2] = c[i][3] = 0.f; }

        uint4 aa = __ldg(&wf[0]);
        #pragma unroll 4
        for (int ks = 0; ks < 24; ks++) {
            uint4 nxt = aa;
            if (ks < 23) nxt = __ldg(&wf[(ks + 1) * 32]);
            u32 bb = ((ks < 16) ? xh0 : xl0) + (u32)((ks & 7) * 16 * 144) + lmoff;
            #pragma unroll
            for (int nt = 0; nt < 4; nt++) {
                u32 f0, f1, f2, f3;
                LDSM_X4_T(f0, f1, f2, f3, bb + nt * 32);
                MMA16816(c[2*nt][0], c[2*nt][1], c[2*nt][2], c[2*nt][3],
                         aa.x, aa.y, aa.z, aa.w, f0, f1);
                MMA16816(c[2*nt+1][0], c[2*nt+1][1], c[2*nt+1][2], c[2*nt+1][3],
                         aa.x, aa.y, aa.z, aa.w, f2, f3);
            }
            aa = nxt;
        }

        float bb0 = __ldg(&Bss[half][r0]);
        float bb1 = __ldg(&Bss[half][r0 + 8]);
        float* op = out + ((size_t)(b * 256 + half * 128) << 10);
        #pragma unroll
        for (int n8 = 0; n8 < 8; n8++) {
            int tok = tok0 + n8 * 8 + fc2;
            float2 o0 = make_float2(c[n8][0] + bb0, c[n8][1] + bb0);
            float2 o1 = make_float2(c[n8][2] + bb1, c[n8][3] + bb1);
            *(float2*)&op[((size_t)r0 << 10) + tok] = o0;
            *(float2*)&op[((size_t)(r0 + 8) << 10) + tok] = o1;
        }
    }
}

// ============================================================
extern "C" void kernel_launch(void* const* d_in, const int* in_sizes, int n_in,
                              void* d_out, int out_size)
{
    const float* x    = (const float*)d_in[0];
    const float* q1w  = (const float*)d_in[1];
    const float* q1b  = (const float*)d_in[2];
    const float* q2w  = (const float*)d_in[3];
    const float* q2b  = (const float*)d_in[4];
    const float* k1w  = (const float*)d_in[5];
    const float* k1b  = (const float*)d_in[6];
    const float* k2w  = (const float*)d_in[7];
    const float* k2b  = (const float*)d_in[8];
    const float* v1w  = (const float*)d_in[9];
    const float* v1b  = (const float*)d_in[10];
    const float* v2w  = (const float*)d_in[11];
    const float* v2b  = (const float*)d_in[12];
    const float* p1w  = (const float*)d_in[13];
    const float* p1b  = (const float*)d_in[14];
    const float* p2w  = (const float*)d_in[15];
    const float* p2b  = (const float*)d_in[16];
    const float* ls   = (const float*)d_in[17];
    const float* m1w  = (const float*)d_in[18];
    const float* m1b  = (const float*)d_in[19];
    const float* m2w  = (const float*)d_in[20];
    float* out = (float*)d_out;

    // qkvgemm sits at app-launch index 3 (the ncu slot).
    wext_kernel<<<768, 256>>>(q1w, q2w, k1w, k2w, v1w, v2w, p1w, p2w);
    tab_kernel<<<(TABN_ + 255) / 256, 256>>>(m1w, m1b, m2w);
    bias_kernel<<<dim3(N_, N_ / 256), 256>>>(ls);
    qkvgemm_kernel<<<dim3(16, 16), 256>>>(x, q1b, q2b, k1b, k2b, v1b, v2b);
    normsplit_kernel<<<dim3(8, 128, 2), 128>>>();
    attn_kernel<<<dim3(N_ / 128, BH_), 256>>>(ls);
    osplit_kernel<<<dim3(8, 128), 256>>>();
    projgemm_kernel<<<dim3(16, 16), 256>>>(p1b, p2b, out);
}